// round 14
// baseline (speedup 1.0000x reference)
#include <cuda_runtime.h>
#include <cuda_fp16.h>
#include <math_constants.h>
#include <cstdint>

#define NN 10000
#define EE 160000
#define RPROJ (NN*25)
#define BCAP 72
#define NP (NN*BCAP)
#define FULLMASK 0xffffffffu

// ---------------- scratch ----------------
__device__ int   g_cnt[NN];            // degree; zeroed by k_attn1 each run
__device__ int   g_colb[NP];           // bucketed neighbor j
__device__ float g_rbf[(size_t)NP*16];
__device__ float g_sh[(size_t)NP*28];  // 25 used, padded to 28 for float4
__device__ __align__(16) float g_eb[2][(size_t)NP*4];
__device__ __align__(16) float g_egg[2][(size_t)NP*8];
__device__ __align__(16) __half g_qh[(size_t)RPROJ*16];
__device__ __align__(16) __half g_kh[(size_t)RPROJ*16];
__device__ __align__(16) __half g_vh[(size_t)RPROJ*16];

// ---------------- helpers ----------------
__device__ __forceinline__ float dot4(float4 a, float4 b) {
    return fmaf(a.x,b.x, fmaf(a.y,b.y, fmaf(a.z,b.z, a.w*b.w)));
}
__device__ __forceinline__ float4 h2f4(uint2 u) {
    __half2 a = *(__half2*)&u.x;
    __half2 b = *(__half2*)&u.y;
    float2 fa = __half22float2(a), fb = __half22float2(b);
    return make_float4(fa.x, fa.y, fb.x, fb.y);
}
__device__ __forceinline__ void fma4(float4& acc, float s, float4 w) {
    acc.x = fmaf(s, w.x, acc.x); acc.y = fmaf(s, w.y, acc.y);
    acc.z = fmaf(s, w.z, acc.z); acc.w = fmaf(s, w.w, acc.w);
}
__device__ __forceinline__ uint2 pack4(float4 a) {
    uint2 o;
    __half2 lo = __floats2half2_rn(a.x, a.y);
    __half2 hi = __floats2half2_rn(a.z, a.w);
    o.x = *(unsigned*)&lo; o.y = *(unsigned*)&hi;
    return o;
}

// ---------------- 1: bucket build + geometry + edge scalars ----------------
__global__ void __launch_bounds__(256) k_build_geom(const int2* __restrict__ ni,
                                                    const float* __restrict__ disp,
                                                    const float* __restrict__ Wb,
                                                    const float* __restrict__ Wg,
                                                    const float* __restrict__ Wg2) {
    __shared__ float4 sW4[96];   // [t][s][f] : t*32 + s*16 + f
    int tid = threadIdx.x;
    if (tid < 32)       sW4[tid] = ((const float4*)Wb)[tid];
    else if (tid < 64)  sW4[tid] = ((const float4*)Wg)[tid-32];
    else if (tid < 96)  sW4[tid] = ((const float4*)Wg2)[tid-64];
    __syncthreads();

    int e = blockIdx.x*256 + tid;
    if (e >= EE) return;
    int2 pr = ni[e];
    int i = pr.x, j = pr.y;
    int slot = atomicAdd(&g_cnt[i], 1);
    if (slot >= BCAP) return;          // statistically impossible for Poisson(16)
    int p = i*BCAP + slot;
    g_colb[p] = j;

    float dx = disp[3*e], dy = disp[3*e+1], dz = disp[3*e+2];
    float d  = sqrtf(dx*dx + dy*dy + dz*dz);
    float ds = fmaxf(d, 1e-9f);
    float inv = 1.0f/ds;
    float x = dx*inv, y = dy*inv, z = dz*inv;

    float env = 0.5f*(cospif(fminf(ds, 5.0f)*0.2f) + 1.0f);
    float t = ds*0.2f;
    float rbf[16];
    if (t < 1e-7f) {
        #pragma unroll
        for (int kk = 0; kk < 16; kk++) rbf[kk] = env;
    } else {
        float s1, c1;
        sincospif(t, &s1, &c1);
        float twoc = 2.0f*c1;
        float invt = env / (CUDART_PI_F * t);
        float skm = 0.0f, sk = s1;
        #pragma unroll
        for (int kk = 0; kk < 16; kk++) {
            rbf[kk] = sk * invt * (1.0f/(float)(kk+1));
            float nx = twoc*sk - skm;
            skm = sk; sk = nx;
        }
    }
    float4* rp = (float4*)(g_rbf + (size_t)p*16);
    rp[0] = make_float4(rbf[0],rbf[1],rbf[2],rbf[3]);
    rp[1] = make_float4(rbf[4],rbf[5],rbf[6],rbf[7]);
    rp[2] = make_float4(rbf[8],rbf[9],rbf[10],rbf[11]);
    rp[3] = make_float4(rbf[12],rbf[13],rbf[14],rbf[15]);

    #pragma unroll
    for (int s = 0; s < 2; s++) {
        float4 ab = make_float4(0,0,0,0), ag = ab, ag2 = ab;
        #pragma unroll
        for (int f = 0; f < 16; f++) {
            float rv = rbf[f];
            fma4(ab,  rv, sW4[s*16+f]);
            fma4(ag,  rv, sW4[32+s*16+f]);
            fma4(ag2, rv, sW4[64+s*16+f]);
        }
        *(float4*)(g_eb[s]  + (size_t)p*4)     = ab;
        *(float4*)(g_egg[s] + (size_t)p*8)     = ag;
        *(float4*)(g_egg[s] + (size_t)p*8 + 4) = ag2;
    }

    float x2 = x*x, y2 = y*y, z2 = z*z;
    float sh[25];
    sh[0]  = 0.28209479177387814f;
    sh[1]  = 0.4886025119029199f*y;
    sh[2]  = 0.4886025119029199f*z;
    sh[3]  = 0.4886025119029199f*x;
    sh[4]  = 1.0925484305920792f*x*y;
    sh[5]  = 1.0925484305920792f*y*z;
    sh[6]  = 0.31539156525252005f*(3.0f*z2 - 1.0f);
    sh[7]  = 1.0925484305920792f*x*z;
    sh[8]  = 0.5462742152960396f*(x2 - y2);
    sh[9]  = 0.5900435899266435f*y*(3.0f*x2 - y2);
    sh[10] = 2.890611442640554f*x*y*z;
    sh[11] = 0.4570457994644658f*y*(5.0f*z2 - 1.0f);
    sh[12] = 0.3731763325901154f*z*(5.0f*z2 - 3.0f);
    sh[13] = 0.4570457994644658f*x*(5.0f*z2 - 1.0f);
    sh[14] = 1.445305721320277f*z*(x2 - y2);
    sh[15] = 0.5900435899266435f*x*(x2 - 3.0f*y2);
    sh[16] = 2.5033429417967046f*x*y*(x2 - y2);
    sh[17] = 1.7701307697799304f*y*z*(3.0f*x2 - y2);
    sh[18] = 0.9461746957575601f*x*y*(7.0f*z2 - 1.0f);
    sh[19] = 0.6690465435572892f*y*z*(7.0f*z2 - 3.0f);
    sh[20] = 0.10578554691520431f*(35.0f*z2*z2 - 30.0f*z2 + 3.0f);
    sh[21] = 0.6690465435572892f*x*z*(7.0f*z2 - 3.0f);
    sh[22] = 0.47308734787878004f*(x2 - y2)*(7.0f*z2 - 1.0f);
    sh[23] = 1.7701307697799304f*x*z*(x2 - 3.0f*y2);
    sh[24] = 0.6258357354491761f*(x2*x2 - 6.0f*x2*y2 + y2*y2);
    float4* shp = (float4*)(g_sh + (size_t)p*28);
    shp[0] = make_float4(sh[0],sh[1],sh[2],sh[3]);
    shp[1] = make_float4(sh[4],sh[5],sh[6],sh[7]);
    shp[2] = make_float4(sh[8],sh[9],sh[10],sh[11]);
    shp[3] = make_float4(sh[12],sh[13],sh[14],sh[15]);
    shp[4] = make_float4(sh[16],sh[17],sh[18],sh[19]);
    shp[5] = make_float4(sh[20],sh[21],sh[22],sh[23]);
    shp[6] = make_float4(sh[24],0.0f,0.0f,0.0f);
}

// ---------------- 2: y0 init + step-0 q/k/v projection (row 0 only) ----------------
__global__ void __launch_bounds__(128) k_initproj0(const float* __restrict__ emb,
                                                   const float* __restrict__ Wrb,
                                                   const float* __restrict__ Wq0,
                                                   const float* __restrict__ Wk0,
                                                   const float* __restrict__ Wv0,
                                                   const int* __restrict__ Z,
                                                   float* __restrict__ y) {
    int tid = threadIdx.x;
    int w = tid >> 5, lane = tid & 31;
    int node = blockIdx.x*4 + w;
    int f = lane & 15, which = lane >> 4;
    int deg = min(g_cnt[node], BCAP);
    int base = node*BCAP;

    float acc = 0.0f;
    for (int sl = which; sl < deg; sl += 2) {
        int p = base + sl;
        int j = g_colb[p];
        int z = Z[j];
        acc = fmaf(g_rbf[(size_t)p*16+f], __ldg(&emb[z*16+f]), acc);
    }
    acc += __shfl_xor_sync(FULLMASK, acc, 16);
    float y0 = 0.0f;
    #pragma unroll
    for (int ff = 0; ff < 16; ff++)
        y0 = fmaf(__shfl_sync(FULLMASK, acc, ff), __ldg(&Wrb[ff*16+f]), y0);

    float* yp = y + (size_t)node*400;
    if (lane < 16) yp[f] = y0;
    float4* yz = (float4*)(yp + 16);
    #pragma unroll
    for (int idx = lane; idx < 96; idx += 32) yz[idx] = make_float4(0,0,0,0);

    // q0 (half A) / k0 (half B), v0 (half A)
    const float* Wqk = (which == 0) ? Wq0 : Wk0;
    float oq = 0.0f, ov = 0.0f;
    #pragma unroll
    for (int ff = 0; ff < 16; ff++) {
        float yv = __shfl_sync(FULLMASK, y0, ff);
        oq = fmaf(yv, __ldg(&Wqk[ff*16+f]), oq);
        ov = fmaf(yv, __ldg(&Wv0[ff*16+f]), ov);
    }
    size_t ro = (size_t)node*400;
    if (which == 0) {
        g_qh[ro+f] = __float2half_rn(oq);
        g_vh[ro+f] = __float2half_rn(ov);
    } else {
        g_kh[ro+f] = __float2half_rn(oq);
    }
}

// ---------------- 3: step-0 attention (only l=0 rows of q/k/v are nonzero) ----------------
__global__ void __launch_bounds__(128) k_attn0(const float* __restrict__ Wo,
                                               float* __restrict__ y) {
    __shared__ float wo[256];
    __shared__ float slw [4][BCAP][4];
    __shared__ float slw2[4][BCAP][4];
    __shared__ float aggS[4][25][17];
    int tid = threadIdx.x;
    wo[tid]     = Wo[tid];
    wo[tid+128] = Wo[tid+128];

    int w4 = tid >> 5, lane = tid & 31;
    int node = blockIdx.x*4 + w4;
    int r = lane >> 2, fq = lane & 3;
    int deg = min(g_cnt[node], BCAP);
    int base = node*BCAP;
    __syncthreads();

    const uint2* qp = (const uint2*)g_qh + (size_t)node*100;
    float4 q0v = h2f4(qp[fq]);
    const float* eb = g_eb[0];

    // pass 1: logits (32 B k0 gather per edge)
    for (int sl = 0; sl < deg; sl++) {
        int p = base + sl;
        int j = g_colb[p];
        const uint2* kp = (const uint2*)g_kh + (size_t)j*100;
        float4 k0v = h2f4(kp[fq]);
        float lg = fmaf(dot4(q0v, k0v), 0.1f, eb[(size_t)p*4+fq]);
        if (lane < 4) slw[w4][sl][lane] = lg;
    }
    __syncwarp();

    // softmax + premultiplied weights
    {
        float mx = -CUDART_INF_F;
        for (int idx = r; idx < deg; idx += 8)
            mx = fmaxf(mx, slw[w4][idx][fq]);
        mx = fmaxf(mx, __shfl_xor_sync(FULLMASK, mx, 4));
        mx = fmaxf(mx, __shfl_xor_sync(FULLMASK, mx, 8));
        mx = fmaxf(mx, __shfl_xor_sync(FULLMASK, mx, 16));
        float sacc = 0.0f;
        for (int idx = r; idx < deg; idx += 8)
            sacc += __expf(slw[w4][idx][fq] - mx);
        sacc += __shfl_xor_sync(FULLMASK, sacc, 4);
        sacc += __shfl_xor_sync(FULLMASK, sacc, 8);
        sacc += __shfl_xor_sync(FULLMASK, sacc, 16);
        float invs = 1.0f/(sacc + 1e-9f);
        const float* gg = g_egg[0];
        for (int idx = r; idx < deg; idx += 8) {
            int p = base + idx;
            float at = __expf(slw[w4][idx][fq] - mx) * invs;
            slw [w4][idx][fq] = at * gg[(size_t)p*8+fq];
            slw2[w4][idx][fq] = at * gg[(size_t)p*8+4+fq];
        }
    }
    __syncwarp();

    // pass 2: aggregation using only v0 (32 B per edge)
    float4 a0 = make_float4(0,0,0,0), a1 = a0, a2 = a0, a3 = a0;
    for (int sl = 0; sl < deg; sl++) {
        int p = base + sl;
        int j = g_colb[p];
        const uint2* vp = (const uint2*)g_vh + (size_t)j*100;
        float4 v0 = h2f4(vp[fq]);
        float wv  = slw [w4][sl][fq];
        float w2v = slw2[w4][sl][fq];
        float shv = (lane < 25) ? g_sh[(size_t)p*28 + lane] : 0.0f;
        float s0 = __shfl_sync(FULLMASK, shv, r);
        float s1 = __shfl_sync(FULLMASK, shv, r+8);
        float s2 = __shfl_sync(FULLMASK, shv, r+16);
        float s3 = __shfl_sync(FULLMASK, shv, 24);
        float t0 = fmaf(wv, s0, (r == 0) ? w2v : 0.0f);
        a0.x = fmaf(t0, v0.x, a0.x); a0.y = fmaf(t0, v0.y, a0.y);
        a0.z = fmaf(t0, v0.z, a0.z); a0.w = fmaf(t0, v0.w, a0.w);
        float t1 = wv*s1;
        a1.x = fmaf(t1, v0.x, a1.x); a1.y = fmaf(t1, v0.y, a1.y);
        a1.z = fmaf(t1, v0.z, a1.z); a1.w = fmaf(t1, v0.w, a1.w);
        float t2 = wv*s2;
        a2.x = fmaf(t2, v0.x, a2.x); a2.y = fmaf(t2, v0.y, a2.y);
        a2.z = fmaf(t2, v0.z, a2.z); a2.w = fmaf(t2, v0.w, a2.w);
        if (lane < 4) {
            float t3 = wv*s3;
            a3.x = fmaf(t3, v0.x, a3.x); a3.y = fmaf(t3, v0.y, a3.y);
            a3.z = fmaf(t3, v0.z, a3.z); a3.w = fmaf(t3, v0.w, a3.w);
        }
    }

    int cb = fq*4;
    aggS[w4][r   ][cb+0]=a0.x; aggS[w4][r   ][cb+1]=a0.y; aggS[w4][r   ][cb+2]=a0.z; aggS[w4][r   ][cb+3]=a0.w;
    aggS[w4][r+8 ][cb+0]=a1.x; aggS[w4][r+8 ][cb+1]=a1.y; aggS[w4][r+8 ][cb+2]=a1.z; aggS[w4][r+8 ][cb+3]=a1.w;
    aggS[w4][r+16][cb+0]=a2.x; aggS[w4][r+16][cb+1]=a2.y; aggS[w4][r+16][cb+2]=a2.z; aggS[w4][r+16][cb+3]=a2.w;
    if (lane < 4) {
        aggS[w4][24][cb+0]=a3.x; aggS[w4][24][cb+1]=a3.y; aggS[w4][24][cb+2]=a3.z; aggS[w4][24][cb+3]=a3.w;
    }
    __syncwarp();

    float* yp = y + (size_t)node*400;
    #pragma unroll
    for (int c = 0; c < 4; c++) {
        int l = r + 8*c;
        if (c == 3) { if (lane >= 4) break; l = 24; }
        float4 o = make_float4(0,0,0,0);
        #pragma unroll
        for (int f2 = 0; f2 < 16; f2++) {
            float af = aggS[w4][l][f2];
            float4 wr = *(const float4*)&wo[f2*16 + cb];
            o.x = fmaf(af, wr.x, o.x); o.y = fmaf(af, wr.y, o.y);
            o.z = fmaf(af, wr.z, o.z); o.w = fmaf(af, wr.w, o.w);
        }
        float4 yv = *(const float4*)&yp[l*16 + cb];
        yv.x += o.x; yv.y += o.y; yv.z += o.z; yv.w += o.w;
        *(float4*)&yp[l*16 + cb] = yv;
    }
}

// ---------------- 4: full q/k/v projection, thread per row, sequential q/k/v ----------------
__global__ void __launch_bounds__(256) k_proj(const float* __restrict__ y,
                                              const float* __restrict__ Wq,
                                              const float* __restrict__ Wk,
                                              const float* __restrict__ Wv) {
    __shared__ float4 sw[192];   // q:[0,64) k:[64,128) v:[128,192)
    int tid = threadIdx.x;
    if (tid < 64)        sw[tid]     = ((const float4*)Wq)[tid];
    else if (tid < 128)  sw[tid]     = ((const float4*)Wk)[tid-64];
    else if (tid < 192)  sw[tid]     = ((const float4*)Wv)[tid-128];
    __syncthreads();

    int r = blockIdx.x*256 + tid;
    if (r >= RPROJ) return;

    const float4* yr4 = (const float4*)(y + (size_t)r*16);
    float4 y0 = yr4[0], y1 = yr4[1], y2 = yr4[2], y3 = yr4[3];
    float yr[16] = {y0.x,y0.y,y0.z,y0.w, y1.x,y1.y,y1.z,y1.w,
                    y2.x,y2.y,y2.z,y2.w, y3.x,y3.y,y3.z,y3.w};

    __half* outs[3] = { g_qh, g_kh, g_vh };
    #pragma unroll
    for (int m = 0; m < 3; m++) {
        const float4* W = sw + m*64;
        float4 a0 = make_float4(0,0,0,0), a1 = a0, a2 = a0, a3 = a0;
        #pragma unroll
        for (int f = 0; f < 16; f++) {
            float yv = yr[f];
            fma4(a0, yv, W[f*4+0]);
            fma4(a1, yv, W[f*4+1]);
            fma4(a2, yv, W[f*4+2]);
            fma4(a3, yv, W[f*4+3]);
        }
        uint4* o4 = (uint4*)(outs[m] + (size_t)r*16);
        uint2 p0, p1;
        p0 = pack4(a0); p1 = pack4(a1); o4[0] = make_uint4(p0.x,p0.y,p1.x,p1.y);
        p0 = pack4(a2); p1 = pack4(a3); o4[1] = make_uint4(p0.x,p0.y,p1.x,p1.y);
    }
}

// ---------------- 5: full attention step 1 + final embed, 8 warps per node ----------------
__global__ void __launch_bounds__(256) k_attn1(const float* __restrict__ Wo,
                                               const float* __restrict__ We,
                                               const float* __restrict__ be,
                                               const float* __restrict__ emb,
                                               const int* __restrict__ Z,
                                               float* __restrict__ y) {
    __shared__ float wo[256];
    __shared__ float sWe[256];
    __shared__ float slw [BCAP][4];
    __shared__ float slw2[BCAP][4];
    __shared__ float aggS[2][25][17];
    __shared__ int   slj [BCAP];
    int tid = threadIdx.x;
    wo[tid]  = Wo[tid];
    sWe[tid] = We[tid];

    int w8 = tid >> 5, lane = tid & 31;
    int node = blockIdx.x;
    int deg = min(g_cnt[node], BCAP);
    int base = node*BCAP;
    if (tid < deg) slj[tid] = g_colb[base + tid];
    __syncthreads();

    // pass 1: logits; 8-way edge split, q in registers
    {
        const uint2* qp = (const uint2*)g_qh + (size_t)node*100;
        float4 q0 = h2f4(qp[lane]), q1 = h2f4(qp[lane+32]), q2 = h2f4(qp[lane+64]);
        float4 q3 = (lane < 4) ? h2f4(qp[lane+96]) : make_float4(0,0,0,0);
        const float* eb = g_eb[1];

        for (int sl = w8; sl < deg; sl += 8) {
            int j0 = slj[sl];
            const uint2* kp0 = (const uint2*)g_kh + (size_t)j0*100;
            float pa = dot4(q0,h2f4(kp0[lane])) + dot4(q1,h2f4(kp0[lane+32]))
                     + dot4(q2,h2f4(kp0[lane+64]));
            if (lane < 4) pa += dot4(q3, h2f4(kp0[lane+96]));
            pa += __shfl_xor_sync(FULLMASK, pa, 4);
            pa += __shfl_xor_sync(FULLMASK, pa, 8);
            pa += __shfl_xor_sync(FULLMASK, pa, 16);
            if (lane < 4)
                slw[sl][lane] = fmaf(pa, 0.1f, eb[(size_t)(base+sl)*4+lane]);
        }
    }
    __syncthreads();

    // softmax: warps 0-3, warp h handles head h
    if (w8 < 4) {
        int h = w8;
        float mx = -CUDART_INF_F;
        for (int idx = lane; idx < deg; idx += 32)
            mx = fmaxf(mx, slw[idx][h]);
        #pragma unroll
        for (int o = 16; o >= 1; o >>= 1)
            mx = fmaxf(mx, __shfl_xor_sync(FULLMASK, mx, o));
        float sacc = 0.0f;
        for (int idx = lane; idx < deg; idx += 32)
            sacc += __expf(slw[idx][h] - mx);
        #pragma unroll
        for (int o = 16; o >= 1; o >>= 1)
            sacc += __shfl_xor_sync(FULLMASK, sacc, o);
        float invs = 1.0f/(sacc + 1e-9f);
        const float* gg = g_egg[1];
        for (int idx = lane; idx < deg; idx += 32) {
            int p = base + idx;
            float at = __expf(slw[idx][h] - mx) * invs;
            slw [idx][h] = at * gg[(size_t)p*8+h];
            slw2[idx][h] = at * gg[(size_t)p*8+4+h];
        }
    }
    __syncthreads();

    // pass 2: warps split (edge-half, l-rows): half = w8>>2, wq = w8&3
    int half = w8 >> 2, wq = w8 & 3;
    int lbase = (wq == 0) ? 0 : 7 + (wq-1)*6;
    int R = (wq == 0) ? 7 : 6;
    int r = lane >> 2, fq = lane & 3;   // fq == head (FH=4)
    bool act = (r < R);
    int lrow = lbase + (act ? r : 0);

    float4 acc = make_float4(0,0,0,0);
    for (int sl = half; sl < deg; sl += 2) {
        int p = base + sl;
        int j = slj[sl];
        const uint2* vp = (const uint2*)g_vh + (size_t)j*100;
        float wv  = slw [sl][fq];
        float w2v = slw2[sl][fq];
        float shv = g_sh[(size_t)p*28 + lrow];
        float4 v0 = h2f4(vp[fq]);
        float4 vA = h2f4(vp[lrow*4 + fq]);
        float c = wv*shv;
        acc.x = fmaf(c, v0.x, fmaf(w2v, vA.x, acc.x));
        acc.y = fmaf(c, v0.y, fmaf(w2v, vA.y, acc.y));
        acc.z = fmaf(c, v0.z, fmaf(w2v, vA.z, acc.z));
        acc.w = fmaf(c, v0.w, fmaf(w2v, vA.w, acc.w));
    }
    if (act) {
        aggS[half][lrow][fq*4+0] = acc.x;
        aggS[half][lrow][fq*4+1] = acc.y;
        aggS[half][lrow][fq*4+2] = acc.z;
        aggS[half][lrow][fq*4+3] = acc.w;
    }
    __syncthreads();

    // epilogue by warps 0-3: y += (aggS[0]+aggS[1]) @ Wo ; fused embed on row 0
    if (w8 < 4 && act) {
        float* yp = y + (size_t)node*400;
        float4 o = make_float4(0,0,0,0);
        #pragma unroll
        for (int f = 0; f < 16; f++) {
            float af = aggS[0][lrow][f] + aggS[1][lrow][f];
            float4 wr = *(const float4*)&wo[f*16 + fq*4];
            o.x = fmaf(af, wr.x, o.x); o.y = fmaf(af, wr.y, o.y);
            o.z = fmaf(af, wr.z, o.z); o.w = fmaf(af, wr.w, o.w);
        }
        if (lrow == 0) {
            int z = Z[node];
            float4 add = *(const float4*)&be[fq*4];
            #pragma unroll
            for (int f = 0; f < 16; f++) {
                float ev = __ldg(&emb[z*16+f]);
                float4 wr = *(const float4*)&sWe[f*16 + fq*4];
                add.x = fmaf(ev, wr.x, add.x); add.y = fmaf(ev, wr.y, add.y);
                add.z = fmaf(ev, wr.z, add.z); add.w = fmaf(ev, wr.w, add.w);
            }
            o.x += add.x; o.y += add.y; o.z += add.z; o.w += add.w;
        }
        float4 yv = *(const float4*)&yp[lrow*16 + fq*4];
        yv.x += o.x; yv.y += o.y; yv.z += o.z; yv.w += o.w;
        *(float4*)&yp[lrow*16 + fq*4] = yv;
    }

    // restore invariant for next graph replay
    if (tid == 0) g_cnt[node] = 0;
}

// ---------------- launch ----------------
extern "C" void kernel_launch(void* const* d_in, const int* in_sizes, int n_in,
                              void* d_out, int out_size) {
    const int*   Z    = (const int*)d_in[0];
    const int2*  ni   = (const int2*)d_in[1];
    const float* disp = (const float*)d_in[2];
    const float* emb  = (const float*)d_in[3];
    const float* We   = (const float*)d_in[4];
    const float* be   = (const float*)d_in[5];
    const float* Wrb  = (const float*)d_in[6];
    const float* Wq   = (const float*)d_in[7];
    const float* Wk   = (const float*)d_in[8];
    const float* Wv   = (const float*)d_in[9];
    const float* Wo   = (const float*)d_in[10];
    const float* Wb   = (const float*)d_in[11];
    const float* Wg   = (const float*)d_in[12];
    const float* Wg2  = (const float*)d_in[13];
    float* y = (float*)d_out;

    k_build_geom<<<(EE+255)/256, 256>>>(ni, disp, Wb, Wg, Wg2);
    k_initproj0 <<<NN/4, 128>>>(emb, Wrb, Wq, Wk, Wv, Z, y);
    k_attn0     <<<NN/4, 128>>>(Wo, y);
    k_proj      <<<(RPROJ+255)/256, 256>>>(y, Wq+256, Wk+256, Wv+256);
    k_attn1     <<<NN, 256>>>(Wo+256, We, be, emb, Z, y);
}

// round 15
// speedup vs baseline: 1.1845x; 1.1845x over previous
#include <cuda_runtime.h>
#include <cuda_fp16.h>
#include <math_constants.h>
#include <cstdint>

#define NN 10000
#define EE 160000
#define RPROJ (NN*25)
#define BCAP 72
#define NP (NN*BCAP)
#define FULLMASK 0xffffffffu

// ---------------- scratch ----------------
__device__ int   g_cnt[NN];            // degree; zeroed by k_attn1 each run
__device__ int   g_colb[NP];           // bucketed neighbor j
__device__ float g_rbf[(size_t)NP*16];
__device__ float g_sh[(size_t)NP*28];  // 25 used, padded to 28 for float4
__device__ __align__(16) float g_eb[2][(size_t)NP*4];
__device__ __align__(16) float g_egg[2][(size_t)NP*8];
__device__ __align__(16) __half g_qh[(size_t)RPROJ*16];
__device__ __align__(16) __half g_kh[(size_t)RPROJ*16];
__device__ __align__(16) __half g_vh[(size_t)RPROJ*16];

// ---------------- helpers ----------------
__device__ __forceinline__ float dot4(float4 a, float4 b) {
    return fmaf(a.x,b.x, fmaf(a.y,b.y, fmaf(a.z,b.z, a.w*b.w)));
}
__device__ __forceinline__ float4 h2f4(uint2 u) {
    __half2 a = *(__half2*)&u.x;
    __half2 b = *(__half2*)&u.y;
    float2 fa = __half22float2(a), fb = __half22float2(b);
    return make_float4(fa.x, fa.y, fb.x, fb.y);
}
__device__ __forceinline__ void fma4(float4& acc, float s, float4 w) {
    acc.x = fmaf(s, w.x, acc.x); acc.y = fmaf(s, w.y, acc.y);
    acc.z = fmaf(s, w.z, acc.z); acc.w = fmaf(s, w.w, acc.w);
}
__device__ __forceinline__ uint2 pack4(float4 a) {
    uint2 o;
    __half2 lo = __floats2half2_rn(a.x, a.y);
    __half2 hi = __floats2half2_rn(a.z, a.w);
    o.x = *(unsigned*)&lo; o.y = *(unsigned*)&hi;
    return o;
}

// ---------------- 1: bucket build + geometry + edge scalars ----------------
__global__ void __launch_bounds__(256) k_build_geom(const int2* __restrict__ ni,
                                                    const float* __restrict__ disp,
                                                    const float* __restrict__ Wb,
                                                    const float* __restrict__ Wg,
                                                    const float* __restrict__ Wg2) {
    __shared__ float4 sW4[96];   // [t][s][f] : t*32 + s*16 + f
    int tid = threadIdx.x;
    if (tid < 32)       sW4[tid] = ((const float4*)Wb)[tid];
    else if (tid < 64)  sW4[tid] = ((const float4*)Wg)[tid-32];
    else if (tid < 96)  sW4[tid] = ((const float4*)Wg2)[tid-64];
    __syncthreads();

    int e = blockIdx.x*256 + tid;
    if (e >= EE) return;
    int2 pr = ni[e];
    int i = pr.x, j = pr.y;
    int slot = atomicAdd(&g_cnt[i], 1);
    if (slot >= BCAP) return;          // statistically impossible for Poisson(16)
    int p = i*BCAP + slot;
    g_colb[p] = j;

    float dx = disp[3*e], dy = disp[3*e+1], dz = disp[3*e+2];
    float d  = sqrtf(dx*dx + dy*dy + dz*dz);
    float ds = fmaxf(d, 1e-9f);
    float inv = 1.0f/ds;
    float x = dx*inv, y = dy*inv, z = dz*inv;

    float env = 0.5f*(cospif(fminf(ds, 5.0f)*0.2f) + 1.0f);
    float t = ds*0.2f;
    float rbf[16];
    if (t < 1e-7f) {
        #pragma unroll
        for (int kk = 0; kk < 16; kk++) rbf[kk] = env;
    } else {
        float s1, c1;
        sincospif(t, &s1, &c1);
        float twoc = 2.0f*c1;
        float invt = env / (CUDART_PI_F * t);
        float skm = 0.0f, sk = s1;
        #pragma unroll
        for (int kk = 0; kk < 16; kk++) {
            rbf[kk] = sk * invt * (1.0f/(float)(kk+1));
            float nx = twoc*sk - skm;
            skm = sk; sk = nx;
        }
    }
    float4* rp = (float4*)(g_rbf + (size_t)p*16);
    rp[0] = make_float4(rbf[0],rbf[1],rbf[2],rbf[3]);
    rp[1] = make_float4(rbf[4],rbf[5],rbf[6],rbf[7]);
    rp[2] = make_float4(rbf[8],rbf[9],rbf[10],rbf[11]);
    rp[3] = make_float4(rbf[12],rbf[13],rbf[14],rbf[15]);

    #pragma unroll
    for (int s = 0; s < 2; s++) {
        float4 ab = make_float4(0,0,0,0), ag = ab, ag2 = ab;
        #pragma unroll
        for (int f = 0; f < 16; f++) {
            float rv = rbf[f];
            fma4(ab,  rv, sW4[s*16+f]);
            fma4(ag,  rv, sW4[32+s*16+f]);
            fma4(ag2, rv, sW4[64+s*16+f]);
        }
        *(float4*)(g_eb[s]  + (size_t)p*4)     = ab;
        *(float4*)(g_egg[s] + (size_t)p*8)     = ag;
        *(float4*)(g_egg[s] + (size_t)p*8 + 4) = ag2;
    }

    float x2 = x*x, y2 = y*y, z2 = z*z;
    float sh[25];
    sh[0]  = 0.28209479177387814f;
    sh[1]  = 0.4886025119029199f*y;
    sh[2]  = 0.4886025119029199f*z;
    sh[3]  = 0.4886025119029199f*x;
    sh[4]  = 1.0925484305920792f*x*y;
    sh[5]  = 1.0925484305920792f*y*z;
    sh[6]  = 0.31539156525252005f*(3.0f*z2 - 1.0f);
    sh[7]  = 1.0925484305920792f*x*z;
    sh[8]  = 0.5462742152960396f*(x2 - y2);
    sh[9]  = 0.5900435899266435f*y*(3.0f*x2 - y2);
    sh[10] = 2.890611442640554f*x*y*z;
    sh[11] = 0.4570457994644658f*y*(5.0f*z2 - 1.0f);
    sh[12] = 0.3731763325901154f*z*(5.0f*z2 - 3.0f);
    sh[13] = 0.4570457994644658f*x*(5.0f*z2 - 1.0f);
    sh[14] = 1.445305721320277f*z*(x2 - y2);
    sh[15] = 0.5900435899266435f*x*(x2 - 3.0f*y2);
    sh[16] = 2.5033429417967046f*x*y*(x2 - y2);
    sh[17] = 1.7701307697799304f*y*z*(3.0f*x2 - y2);
    sh[18] = 0.9461746957575601f*x*y*(7.0f*z2 - 1.0f);
    sh[19] = 0.6690465435572892f*y*z*(7.0f*z2 - 3.0f);
    sh[20] = 0.10578554691520431f*(35.0f*z2*z2 - 30.0f*z2 + 3.0f);
    sh[21] = 0.6690465435572892f*x*z*(7.0f*z2 - 3.0f);
    sh[22] = 0.47308734787878004f*(x2 - y2)*(7.0f*z2 - 1.0f);
    sh[23] = 1.7701307697799304f*x*z*(x2 - 3.0f*y2);
    sh[24] = 0.6258357354491761f*(x2*x2 - 6.0f*x2*y2 + y2*y2);
    float4* shp = (float4*)(g_sh + (size_t)p*28);
    shp[0] = make_float4(sh[0],sh[1],sh[2],sh[3]);
    shp[1] = make_float4(sh[4],sh[5],sh[6],sh[7]);
    shp[2] = make_float4(sh[8],sh[9],sh[10],sh[11]);
    shp[3] = make_float4(sh[12],sh[13],sh[14],sh[15]);
    shp[4] = make_float4(sh[16],sh[17],sh[18],sh[19]);
    shp[5] = make_float4(sh[20],sh[21],sh[22],sh[23]);
    shp[6] = make_float4(sh[24],0.0f,0.0f,0.0f);
}

// ---------------- 2: y0 init + step-0 q/k/v projection (row 0 only) ----------------
__global__ void __launch_bounds__(128) k_initproj0(const float* __restrict__ emb,
                                                   const float* __restrict__ Wrb,
                                                   const float* __restrict__ Wq0,
                                                   const float* __restrict__ Wk0,
                                                   const float* __restrict__ Wv0,
                                                   const int* __restrict__ Z,
                                                   float* __restrict__ y) {
    int tid = threadIdx.x;
    int w = tid >> 5, lane = tid & 31;
    int node = blockIdx.x*4 + w;
    int f = lane & 15, which = lane >> 4;
    int deg = min(g_cnt[node], BCAP);
    int base = node*BCAP;

    float acc = 0.0f;
    for (int sl = which; sl < deg; sl += 2) {
        int p = base + sl;
        int j = g_colb[p];
        int z = Z[j];
        acc = fmaf(g_rbf[(size_t)p*16+f], __ldg(&emb[z*16+f]), acc);
    }
    acc += __shfl_xor_sync(FULLMASK, acc, 16);
    float y0 = 0.0f;
    #pragma unroll
    for (int ff = 0; ff < 16; ff++)
        y0 = fmaf(__shfl_sync(FULLMASK, acc, ff), __ldg(&Wrb[ff*16+f]), y0);

    float* yp = y + (size_t)node*400;
    if (lane < 16) yp[f] = y0;
    float4* yz = (float4*)(yp + 16);
    #pragma unroll
    for (int idx = lane; idx < 96; idx += 32) yz[idx] = make_float4(0,0,0,0);

    // q0 (half A) / k0 (half B), v0 (half A)
    const float* Wqk = (which == 0) ? Wq0 : Wk0;
    float oq = 0.0f, ov = 0.0f;
    #pragma unroll
    for (int ff = 0; ff < 16; ff++) {
        float yv = __shfl_sync(FULLMASK, y0, ff);
        oq = fmaf(yv, __ldg(&Wqk[ff*16+f]), oq);
        ov = fmaf(yv, __ldg(&Wv0[ff*16+f]), ov);
    }
    size_t ro = (size_t)node*400;
    if (which == 0) {
        g_qh[ro+f] = __float2half_rn(oq);
        g_vh[ro+f] = __float2half_rn(ov);
    } else {
        g_kh[ro+f] = __float2half_rn(oq);
    }
}

// ---------------- 3: step-0 attention; pass 1 lane-per-edge ----------------
__global__ void __launch_bounds__(128) k_attn0(const float* __restrict__ Wo,
                                               float* __restrict__ y) {
    __shared__ float wo[256];
    __shared__ float slw [4][BCAP][4];
    __shared__ float slw2[4][BCAP][4];
    __shared__ float aggS[4][25][17];
    int tid = threadIdx.x;
    wo[tid]     = Wo[tid];
    wo[tid+128] = Wo[tid+128];

    int w4 = tid >> 5, lane = tid & 31;
    int node = blockIdx.x*4 + w4;
    int r = lane >> 2, fq = lane & 3;
    int deg = min(g_cnt[node], BCAP);
    int base = node*BCAP;
    __syncthreads();

    const uint2* qp = (const uint2*)g_qh + (size_t)node*100;
    float4 q0v = h2f4(qp[fq]);
    const float* eb = g_eb[0];

    // pass 1: logits; lane (g=r, fq) handles edge sl0+r entirely in-lane
    for (int sl0 = 0; sl0 < deg; sl0 += 8) {
        int sl = sl0 + r;
        if (sl < deg) {
            int p = base + sl;
            int j = g_colb[p];
            const uint2* kp = (const uint2*)g_kh + (size_t)j*100;
            float4 k0v = h2f4(kp[fq]);
            slw[w4][sl][fq] = fmaf(dot4(q0v, k0v), 0.1f, eb[(size_t)p*4+fq]);
        }
    }
    __syncwarp();

    // softmax + premultiplied weights
    {
        float mx = -CUDART_INF_F;
        for (int idx = r; idx < deg; idx += 8)
            mx = fmaxf(mx, slw[w4][idx][fq]);
        mx = fmaxf(mx, __shfl_xor_sync(FULLMASK, mx, 4));
        mx = fmaxf(mx, __shfl_xor_sync(FULLMASK, mx, 8));
        mx = fmaxf(mx, __shfl_xor_sync(FULLMASK, mx, 16));
        float sacc = 0.0f;
        for (int idx = r; idx < deg; idx += 8)
            sacc += __expf(slw[w4][idx][fq] - mx);
        sacc += __shfl_xor_sync(FULLMASK, sacc, 4);
        sacc += __shfl_xor_sync(FULLMASK, sacc, 8);
        sacc += __shfl_xor_sync(FULLMASK, sacc, 16);
        float invs = 1.0f/(sacc + 1e-9f);
        const float* gg = g_egg[0];
        for (int idx = r; idx < deg; idx += 8) {
            int p = base + idx;
            float at = __expf(slw[w4][idx][fq] - mx) * invs;
            slw [w4][idx][fq] = at * gg[(size_t)p*8+fq];
            slw2[w4][idx][fq] = at * gg[(size_t)p*8+4+fq];
        }
    }
    __syncwarp();

    // pass 2: aggregation using only v0 (32 B per edge)
    float4 a0 = make_float4(0,0,0,0), a1 = a0, a2 = a0, a3 = a0;
    for (int sl = 0; sl < deg; sl++) {
        int p = base + sl;
        int j = g_colb[p];
        const uint2* vp = (const uint2*)g_vh + (size_t)j*100;
        float4 v0 = h2f4(vp[fq]);
        float wv  = slw [w4][sl][fq];
        float w2v = slw2[w4][sl][fq];
        float shv = (lane < 25) ? g_sh[(size_t)p*28 + lane] : 0.0f;
        float s0 = __shfl_sync(FULLMASK, shv, r);
        float s1 = __shfl_sync(FULLMASK, shv, r+8);
        float s2 = __shfl_sync(FULLMASK, shv, r+16);
        float s3 = __shfl_sync(FULLMASK, shv, 24);
        float t0 = fmaf(wv, s0, (r == 0) ? w2v : 0.0f);
        a0.x = fmaf(t0, v0.x, a0.x); a0.y = fmaf(t0, v0.y, a0.y);
        a0.z = fmaf(t0, v0.z, a0.z); a0.w = fmaf(t0, v0.w, a0.w);
        float t1 = wv*s1;
        a1.x = fmaf(t1, v0.x, a1.x); a1.y = fmaf(t1, v0.y, a1.y);
        a1.z = fmaf(t1, v0.z, a1.z); a1.w = fmaf(t1, v0.w, a1.w);
        float t2 = wv*s2;
        a2.x = fmaf(t2, v0.x, a2.x); a2.y = fmaf(t2, v0.y, a2.y);
        a2.z = fmaf(t2, v0.z, a2.z); a2.w = fmaf(t2, v0.w, a2.w);
        if (lane < 4) {
            float t3 = wv*s3;
            a3.x = fmaf(t3, v0.x, a3.x); a3.y = fmaf(t3, v0.y, a3.y);
            a3.z = fmaf(t3, v0.z, a3.z); a3.w = fmaf(t3, v0.w, a3.w);
        }
    }

    int cb = fq*4;
    aggS[w4][r   ][cb+0]=a0.x; aggS[w4][r   ][cb+1]=a0.y; aggS[w4][r   ][cb+2]=a0.z; aggS[w4][r   ][cb+3]=a0.w;
    aggS[w4][r+8 ][cb+0]=a1.x; aggS[w4][r+8 ][cb+1]=a1.y; aggS[w4][r+8 ][cb+2]=a1.z; aggS[w4][r+8 ][cb+3]=a1.w;
    aggS[w4][r+16][cb+0]=a2.x; aggS[w4][r+16][cb+1]=a2.y; aggS[w4][r+16][cb+2]=a2.z; aggS[w4][r+16][cb+3]=a2.w;
    if (lane < 4) {
        aggS[w4][24][cb+0]=a3.x; aggS[w4][24][cb+1]=a3.y; aggS[w4][24][cb+2]=a3.z; aggS[w4][24][cb+3]=a3.w;
    }
    __syncwarp();

    float* yp = y + (size_t)node*400;
    #pragma unroll
    for (int c = 0; c < 4; c++) {
        int l = r + 8*c;
        if (c == 3) { if (lane >= 4) break; l = 24; }
        float4 o = make_float4(0,0,0,0);
        #pragma unroll
        for (int f2 = 0; f2 < 16; f2++) {
            float af = aggS[w4][l][f2];
            float4 wr = *(const float4*)&wo[f2*16 + cb];
            o.x = fmaf(af, wr.x, o.x); o.y = fmaf(af, wr.y, o.y);
            o.z = fmaf(af, wr.z, o.z); o.w = fmaf(af, wr.w, o.w);
        }
        float4 yv = *(const float4*)&yp[l*16 + cb];
        yv.x += o.x; yv.y += o.y; yv.z += o.z; yv.w += o.w;
        *(float4*)&yp[l*16 + cb] = yv;
    }
}

// ---------------- 4: full q/k/v projection, thread per row, sequential q/k/v ----------------
__global__ void __launch_bounds__(256) k_proj(const float* __restrict__ y,
                                              const float* __restrict__ Wq,
                                              const float* __restrict__ Wk,
                                              const float* __restrict__ Wv) {
    __shared__ float4 sw[192];   // q:[0,64) k:[64,128) v:[128,192)
    int tid = threadIdx.x;
    if (tid < 64)        sw[tid]     = ((const float4*)Wq)[tid];
    else if (tid < 128)  sw[tid]     = ((const float4*)Wk)[tid-64];
    else if (tid < 192)  sw[tid]     = ((const float4*)Wv)[tid-128];
    __syncthreads();

    int r = blockIdx.x*256 + tid;
    if (r >= RPROJ) return;

    const float4* yr4 = (const float4*)(y + (size_t)r*16);
    float4 y0 = yr4[0], y1 = yr4[1], y2 = yr4[2], y3 = yr4[3];
    float yr[16] = {y0.x,y0.y,y0.z,y0.w, y1.x,y1.y,y1.z,y1.w,
                    y2.x,y2.y,y2.z,y2.w, y3.x,y3.y,y3.z,y3.w};

    __half* outs[3] = { g_qh, g_kh, g_vh };
    #pragma unroll
    for (int m = 0; m < 3; m++) {
        const float4* W = sw + m*64;
        float4 a0 = make_float4(0,0,0,0), a1 = a0, a2 = a0, a3 = a0;
        #pragma unroll
        for (int f = 0; f < 16; f++) {
            float yv = yr[f];
            fma4(a0, yv, W[f*4+0]);
            fma4(a1, yv, W[f*4+1]);
            fma4(a2, yv, W[f*4+2]);
            fma4(a3, yv, W[f*4+3]);
        }
        uint4* o4 = (uint4*)(outs[m] + (size_t)r*16);
        uint2 p0, p1;
        p0 = pack4(a0); p1 = pack4(a1); o4[0] = make_uint4(p0.x,p0.y,p1.x,p1.y);
        p0 = pack4(a2); p1 = pack4(a3); o4[1] = make_uint4(p0.x,p0.y,p1.x,p1.y);
    }
}

// ---------------- 5: full attention step 1 + final embed, block per node ----------------
__global__ void __launch_bounds__(128) k_attn1(const float* __restrict__ Wo,
                                               const float* __restrict__ We,
                                               const float* __restrict__ be,
                                               const float* __restrict__ emb,
                                               const int* __restrict__ Z,
                                               float* __restrict__ y) {
    __shared__ float wo[256];
    __shared__ float sWe[256];
    __shared__ float slw [BCAP][4];
    __shared__ float slw2[BCAP][4];
    __shared__ float aggS[25][17];
    int tid = threadIdx.x;
    wo[tid]      = Wo[tid];
    wo[tid+128]  = Wo[tid+128];
    sWe[tid]     = We[tid];
    sWe[tid+128] = We[tid+128];

    int w4 = tid >> 5, lane = tid & 31;
    int node = blockIdx.x;
    int deg = min(g_cnt[node], BCAP);
    int base = node*BCAP;
    __syncthreads();

    // pass 1: logits; warps split edges 4-way, q in registers
    {
        const uint2* qp = (const uint2*)g_qh + (size_t)node*100;
        float4 q0 = h2f4(qp[lane]), q1 = h2f4(qp[lane+32]), q2 = h2f4(qp[lane+64]);
        float4 q3 = (lane < 4) ? h2f4(qp[lane+96]) : make_float4(0,0,0,0);
        const float* eb = g_eb[1];

        for (int sl = w4; sl < deg; sl += 4) {
            int p = base + sl;
            int j0 = g_colb[p];
            const uint2* kp0 = (const uint2*)g_kh + (size_t)j0*100;
            float pa = dot4(q0,h2f4(kp0[lane])) + dot4(q1,h2f4(kp0[lane+32]))
                     + dot4(q2,h2f4(kp0[lane+64]));
            if (lane < 4) pa += dot4(q3, h2f4(kp0[lane+96]));
            pa += __shfl_xor_sync(FULLMASK, pa, 4);
            pa += __shfl_xor_sync(FULLMASK, pa, 8);
            pa += __shfl_xor_sync(FULLMASK, pa, 16);
            if (lane < 4)
                slw[sl][lane] = fmaf(pa, 0.1f, eb[(size_t)p*4+lane]);
        }
    }
    __syncthreads();

    // softmax: warp w4 handles head h = w4
    {
        int h = w4;
        float mx = -CUDART_INF_F;
        for (int idx = lane; idx < deg; idx += 32)
            mx = fmaxf(mx, slw[idx][h]);
        #pragma unroll
        for (int o = 16; o >= 1; o >>= 1)
            mx = fmaxf(mx, __shfl_xor_sync(FULLMASK, mx, o));
        float sacc = 0.0f;
        for (int idx = lane; idx < deg; idx += 32)
            sacc += __expf(slw[idx][h] - mx);
        #pragma unroll
        for (int o = 16; o >= 1; o >>= 1)
            sacc += __shfl_xor_sync(FULLMASK, sacc, o);
        float invs = 1.0f/(sacc + 1e-9f);
        const float* gg = g_egg[1];
        for (int idx = lane; idx < deg; idx += 32) {
            int p = base + idx;
            float at = __expf(slw[idx][h] - mx) * invs;
            slw [idx][h] = at * gg[(size_t)p*8+h];
            slw2[idx][h] = at * gg[(size_t)p*8+4+h];
        }
    }
    __syncthreads();

    // pass 2: aggregation; warps split l-rows (7/6/6/6)
    int lbase = (w4 == 0) ? 0 : 7 + (w4-1)*6;
    int R = (w4 == 0) ? 7 : 6;
    int r = lane >> 2, fq = lane & 3;   // fq == head (FH=4)
    bool act = (r < R);
    int lrow = lbase + (act ? r : 0);

    float4 acc = make_float4(0,0,0,0);
    #pragma unroll 2
    for (int sl = 0; sl < deg; sl++) {
        int p = base + sl;
        int j = g_colb[p];
        const uint2* vp = (const uint2*)g_vh + (size_t)j*100;
        float wv  = slw [sl][fq];
        float w2v = slw2[sl][fq];
        float shv = g_sh[(size_t)p*28 + lrow];
        float4 v0 = h2f4(vp[fq]);
        float4 vA = h2f4(vp[lrow*4 + fq]);
        float c = wv*shv;
        acc.x = fmaf(c, v0.x, fmaf(w2v, vA.x, acc.x));
        acc.y = fmaf(c, v0.y, fmaf(w2v, vA.y, acc.y));
        acc.z = fmaf(c, v0.z, fmaf(w2v, vA.z, acc.z));
        acc.w = fmaf(c, v0.w, fmaf(w2v, vA.w, acc.w));
    }
    if (act) {
        aggS[lrow][fq*4+0] = acc.x;
        aggS[lrow][fq*4+1] = acc.y;
        aggS[lrow][fq*4+2] = acc.z;
        aggS[lrow][fq*4+3] = acc.w;
    }
    __syncwarp();

    // epilogue: y += agg @ Wo ; fuse final embed on row 0
    if (act) {
        float* yp = y + (size_t)node*400;
        float4 o = make_float4(0,0,0,0);
        #pragma unroll
        for (int f = 0; f < 16; f++) {
            float af = aggS[lrow][f];
            float4 wr = *(const float4*)&wo[f*16 + fq*4];
            o.x = fmaf(af, wr.x, o.x); o.y = fmaf(af, wr.y, o.y);
            o.z = fmaf(af, wr.z, o.z); o.w = fmaf(af, wr.w, o.w);
        }
        if (lrow == 0) {
            int z = Z[node];
            float4 add = *(const float4*)&be[fq*4];
            #pragma unroll
            for (int f = 0; f < 16; f++) {
                float ev = __ldg(&emb[z*16+f]);
                float4 wr = *(const float4*)&sWe[f*16 + fq*4];
                add.x = fmaf(ev, wr.x, add.x); add.y = fmaf(ev, wr.y, add.y);
                add.z = fmaf(ev, wr.z, add.z); add.w = fmaf(ev, wr.w, add.w);
            }
            o.x += add.x; o.y += add.y; o.z += add.z; o.w += add.w;
        }
        float4 yv = *(const float4*)&yp[lrow*16 + fq*4];
        yv.x += o.x; yv.y += o.y; yv.z += o.z; yv.w += o.w;
        *(float4*)&yp[lrow*16 + fq*4] = yv;
    }

    // restore invariant for next graph replay
    if (tid == 0) g_cnt[node] = 0;
}

// ---------------- launch ----------------
extern "C" void kernel_launch(void* const* d_in, const int* in_sizes, int n_in,
                              void* d_out, int out_size) {
    const int*   Z    = (const int*)d_in[0];
    const int2*  ni   = (const int2*)d_in[1];
    const float* disp = (const float*)d_in[2];
    const float* emb  = (const float*)d_in[3];
    const float* We   = (const float*)d_in[4];
    const float* be   = (const float*)d_in[5];
    const float* Wrb  = (const float*)d_in[6];
    const float* Wq   = (const float*)d_in[7];
    const float* Wk   = (const float*)d_in[8];
    const float* Wv   = (const float*)d_in[9];
    const float* Wo   = (const float*)d_in[10];
    const float* Wb   = (const float*)d_in[11];
    const float* Wg   = (const float*)d_in[12];
    const float* Wg2  = (const float*)d_in[13];
    float* y = (float*)d_out;

    k_build_geom<<<(EE+255)/256, 256>>>(ni, disp, Wb, Wg, Wg2);
    k_initproj0 <<<NN/4, 128>>>(emb, Wrb, Wq, Wk, Wv, Z, y);
    k_attn0     <<<NN/4, 128>>>(Wo, y);
    k_proj      <<<(RPROJ+255)/256, 256>>>(y, Wq+256, Wk+256, Wv+256);
    k_attn1     <<<NN, 128>>>(Wo+256, We, be, emb, Z, y);
}

// round 16
// speedup vs baseline: 1.2530x; 1.0579x over previous
#include <cuda_runtime.h>
#include <cuda_fp16.h>
#include <math_constants.h>
#include <cstdint>

#define NN 10000
#define EE 160000
#define RPROJ (NN*25)
#define BCAP 72
#define NP (NN*BCAP)
#define FULLMASK 0xffffffffu

// ---------------- scratch ----------------
__device__ int   g_cnt[NN];            // degree; zeroed by k_attn1 each run
__device__ int   g_colb[NP];           // bucketed neighbor j
__device__ float g_rbf[(size_t)NP*16];
__device__ __align__(16) __half g_shh[(size_t)NP*32];  // 25 used, padded to 32 halves
__device__ __align__(16) float g_eb[2][(size_t)NP*4];
__device__ __align__(16) float g_egg[2][(size_t)NP*8];
__device__ __align__(16) __half g_qh[(size_t)RPROJ*16];
__device__ __align__(16) __half g_kh[(size_t)RPROJ*16];
__device__ __align__(16) __half g_vh[(size_t)RPROJ*16];

// ---------------- helpers ----------------
__device__ __forceinline__ float dot4(float4 a, float4 b) {
    return fmaf(a.x,b.x, fmaf(a.y,b.y, fmaf(a.z,b.z, a.w*b.w)));
}
__device__ __forceinline__ float4 h2f4(uint2 u) {
    __half2 a = *(__half2*)&u.x;
    __half2 b = *(__half2*)&u.y;
    float2 fa = __half22float2(a), fb = __half22float2(b);
    return make_float4(fa.x, fa.y, fb.x, fb.y);
}
__device__ __forceinline__ void fma4(float4& acc, float s, float4 w) {
    acc.x = fmaf(s, w.x, acc.x); acc.y = fmaf(s, w.y, acc.y);
    acc.z = fmaf(s, w.z, acc.z); acc.w = fmaf(s, w.w, acc.w);
}
__device__ __forceinline__ uint2 pack4(float4 a) {
    uint2 o;
    __half2 lo = __floats2half2_rn(a.x, a.y);
    __half2 hi = __floats2half2_rn(a.z, a.w);
    o.x = *(unsigned*)&lo; o.y = *(unsigned*)&hi;
    return o;
}
__device__ __forceinline__ unsigned h2u(__half2 v) { return *(unsigned*)&v; }

// ---------------- 1: bucket build + geometry + edge scalars ----------------
__global__ void __launch_bounds__(256) k_build_geom(const int2* __restrict__ ni,
                                                    const float* __restrict__ disp,
                                                    const float* __restrict__ Wb,
                                                    const float* __restrict__ Wg,
                                                    const float* __restrict__ Wg2) {
    __shared__ float4 sW4[96];   // [t][s][f] : t*32 + s*16 + f
    int tid = threadIdx.x;
    if (tid < 32)       sW4[tid] = ((const float4*)Wb)[tid];
    else if (tid < 64)  sW4[tid] = ((const float4*)Wg)[tid-32];
    else if (tid < 96)  sW4[tid] = ((const float4*)Wg2)[tid-64];
    __syncthreads();

    int e = blockIdx.x*256 + tid;
    if (e >= EE) return;
    int2 pr = ni[e];
    int i = pr.x, j = pr.y;
    int slot = atomicAdd(&g_cnt[i], 1);
    if (slot >= BCAP) return;          // statistically impossible for Poisson(16)
    int p = i*BCAP + slot;
    g_colb[p] = j;

    float dx = disp[3*e], dy = disp[3*e+1], dz = disp[3*e+2];
    float d  = sqrtf(dx*dx + dy*dy + dz*dz);
    float ds = fmaxf(d, 1e-9f);
    float inv = 1.0f/ds;
    float x = dx*inv, y = dy*inv, z = dz*inv;

    float env = 0.5f*(cospif(fminf(ds, 5.0f)*0.2f) + 1.0f);
    float t = ds*0.2f;
    float rbf[16];
    if (t < 1e-7f) {
        #pragma unroll
        for (int kk = 0; kk < 16; kk++) rbf[kk] = env;
    } else {
        float s1, c1;
        sincospif(t, &s1, &c1);
        float twoc = 2.0f*c1;
        float invt = env / (CUDART_PI_F * t);
        float skm = 0.0f, sk = s1;
        #pragma unroll
        for (int kk = 0; kk < 16; kk++) {
            rbf[kk] = sk * invt * (1.0f/(float)(kk+1));
            float nx = twoc*sk - skm;
            skm = sk; sk = nx;
        }
    }
    float4* rp = (float4*)(g_rbf + (size_t)p*16);
    rp[0] = make_float4(rbf[0],rbf[1],rbf[2],rbf[3]);
    rp[1] = make_float4(rbf[4],rbf[5],rbf[6],rbf[7]);
    rp[2] = make_float4(rbf[8],rbf[9],rbf[10],rbf[11]);
    rp[3] = make_float4(rbf[12],rbf[13],rbf[14],rbf[15]);

    #pragma unroll
    for (int s = 0; s < 2; s++) {
        float4 ab = make_float4(0,0,0,0), ag = ab, ag2 = ab;
        #pragma unroll
        for (int f = 0; f < 16; f++) {
            float rv = rbf[f];
            fma4(ab,  rv, sW4[s*16+f]);
            fma4(ag,  rv, sW4[32+s*16+f]);
            fma4(ag2, rv, sW4[64+s*16+f]);
        }
        *(float4*)(g_eb[s]  + (size_t)p*4)     = ab;
        *(float4*)(g_egg[s] + (size_t)p*8)     = ag;
        *(float4*)(g_egg[s] + (size_t)p*8 + 4) = ag2;
    }

    float x2 = x*x, y2 = y*y, z2 = z*z;
    float sh[25];
    sh[0]  = 0.28209479177387814f;
    sh[1]  = 0.4886025119029199f*y;
    sh[2]  = 0.4886025119029199f*z;
    sh[3]  = 0.4886025119029199f*x;
    sh[4]  = 1.0925484305920792f*x*y;
    sh[5]  = 1.0925484305920792f*y*z;
    sh[6]  = 0.31539156525252005f*(3.0f*z2 - 1.0f);
    sh[7]  = 1.0925484305920792f*x*z;
    sh[8]  = 0.5462742152960396f*(x2 - y2);
    sh[9]  = 0.5900435899266435f*y*(3.0f*x2 - y2);
    sh[10] = 2.890611442640554f*x*y*z;
    sh[11] = 0.4570457994644658f*y*(5.0f*z2 - 1.0f);
    sh[12] = 0.3731763325901154f*z*(5.0f*z2 - 3.0f);
    sh[13] = 0.4570457994644658f*x*(5.0f*z2 - 1.0f);
    sh[14] = 1.445305721320277f*z*(x2 - y2);
    sh[15] = 0.5900435899266435f*x*(x2 - 3.0f*y2);
    sh[16] = 2.5033429417967046f*x*y*(x2 - y2);
    sh[17] = 1.7701307697799304f*y*z*(3.0f*x2 - y2);
    sh[18] = 0.9461746957575601f*x*y*(7.0f*z2 - 1.0f);
    sh[19] = 0.6690465435572892f*y*z*(7.0f*z2 - 3.0f);
    sh[20] = 0.10578554691520431f*(35.0f*z2*z2 - 30.0f*z2 + 3.0f);
    sh[21] = 0.6690465435572892f*x*z*(7.0f*z2 - 3.0f);
    sh[22] = 0.47308734787878004f*(x2 - y2)*(7.0f*z2 - 1.0f);
    sh[23] = 1.7701307697799304f*x*z*(x2 - 3.0f*y2);
    sh[24] = 0.6258357354491761f*(x2*x2 - 6.0f*x2*y2 + y2*y2);

    unsigned hp[13];
    #pragma unroll
    for (int ii = 0; ii < 12; ii++)
        hp[ii] = h2u(__floats2half2_rn(sh[2*ii], sh[2*ii+1]));
    hp[12] = h2u(__floats2half2_rn(sh[24], 0.0f));
    uint4* o4 = (uint4*)(g_shh + (size_t)p*32);
    o4[0] = make_uint4(hp[0], hp[1], hp[2], hp[3]);
    o4[1] = make_uint4(hp[4], hp[5], hp[6], hp[7]);
    o4[2] = make_uint4(hp[8], hp[9], hp[10], hp[11]);
    o4[3] = make_uint4(hp[12], 0u, 0u, 0u);
}

// ---------------- 2: y0 init + step-0 q/k/v projection (row 0 only) ----------------
__global__ void __launch_bounds__(128) k_initproj0(const float* __restrict__ emb,
                                                   const float* __restrict__ Wrb,
                                                   const float* __restrict__ Wq0,
                                                   const float* __restrict__ Wk0,
                                                   const float* __restrict__ Wv0,
                                                   const int* __restrict__ Z,
                                                   float* __restrict__ y) {
    int tid = threadIdx.x;
    int w = tid >> 5, lane = tid & 31;
    int node = blockIdx.x*4 + w;
    int f = lane & 15, which = lane >> 4;
    int deg = min(g_cnt[node], BCAP);
    int base = node*BCAP;

    float acc = 0.0f;
    for (int sl = which; sl < deg; sl += 2) {
        int p = base + sl;
        int j = g_colb[p];
        int z = Z[j];
        acc = fmaf(g_rbf[(size_t)p*16+f], __ldg(&emb[z*16+f]), acc);
    }
    acc += __shfl_xor_sync(FULLMASK, acc, 16);
    float y0 = 0.0f;
    #pragma unroll
    for (int ff = 0; ff < 16; ff++)
        y0 = fmaf(__shfl_sync(FULLMASK, acc, ff), __ldg(&Wrb[ff*16+f]), y0);

    float* yp = y + (size_t)node*400;
    if (lane < 16) yp[f] = y0;
    float4* yz = (float4*)(yp + 16);
    #pragma unroll
    for (int idx = lane; idx < 96; idx += 32) yz[idx] = make_float4(0,0,0,0);

    // q0 (half A) / k0 (half B), v0 (half A)
    const float* Wqk = (which == 0) ? Wq0 : Wk0;
    float oq = 0.0f, ov = 0.0f;
    #pragma unroll
    for (int ff = 0; ff < 16; ff++) {
        float yv = __shfl_sync(FULLMASK, y0, ff);
        oq = fmaf(yv, __ldg(&Wqk[ff*16+f]), oq);
        ov = fmaf(yv, __ldg(&Wv0[ff*16+f]), ov);
    }
    size_t ro = (size_t)node*400;
    if (which == 0) {
        g_qh[ro+f] = __float2half_rn(oq);
        g_vh[ro+f] = __float2half_rn(ov);
    } else {
        g_kh[ro+f] = __float2half_rn(oq);
    }
}

// ---------------- 3: step-0 attention; pass 1 lane-per-edge ----------------
__global__ void __launch_bounds__(128) k_attn0(const float* __restrict__ Wo,
                                               float* __restrict__ y) {
    __shared__ float wo[256];
    __shared__ float slw [4][BCAP][4];
    __shared__ float slw2[4][BCAP][4];
    __shared__ float aggS[4][25][17];
    int tid = threadIdx.x;
    wo[tid]     = Wo[tid];
    wo[tid+128] = Wo[tid+128];

    int w4 = tid >> 5, lane = tid & 31;
    int node = blockIdx.x*4 + w4;
    int r = lane >> 2, fq = lane & 3;
    int deg = min(g_cnt[node], BCAP);
    int base = node*BCAP;
    __syncthreads();

    const uint2* qp = (const uint2*)g_qh + (size_t)node*100;
    float4 q0v = h2f4(qp[fq]);
    const float* eb = g_eb[0];

    // pass 1: logits; lane (g=r, fq) handles edge sl0+r entirely in-lane
    for (int sl0 = 0; sl0 < deg; sl0 += 8) {
        int sl = sl0 + r;
        if (sl < deg) {
            int p = base + sl;
            int j = g_colb[p];
            const uint2* kp = (const uint2*)g_kh + (size_t)j*100;
            float4 k0v = h2f4(kp[fq]);
            slw[w4][sl][fq] = fmaf(dot4(q0v, k0v), 0.1f, eb[(size_t)p*4+fq]);
        }
    }
    __syncwarp();

    // softmax + premultiplied weights
    {
        float mx = -CUDART_INF_F;
        for (int idx = r; idx < deg; idx += 8)
            mx = fmaxf(mx, slw[w4][idx][fq]);
        mx = fmaxf(mx, __shfl_xor_sync(FULLMASK, mx, 4));
        mx = fmaxf(mx, __shfl_xor_sync(FULLMASK, mx, 8));
        mx = fmaxf(mx, __shfl_xor_sync(FULLMASK, mx, 16));
        float sacc = 0.0f;
        for (int idx = r; idx < deg; idx += 8)
            sacc += __expf(slw[w4][idx][fq] - mx);
        sacc += __shfl_xor_sync(FULLMASK, sacc, 4);
        sacc += __shfl_xor_sync(FULLMASK, sacc, 8);
        sacc += __shfl_xor_sync(FULLMASK, sacc, 16);
        float invs = 1.0f/(sacc + 1e-9f);
        const float* gg = g_egg[0];
        for (int idx = r; idx < deg; idx += 8) {
            int p = base + idx;
            float at = __expf(slw[w4][idx][fq] - mx) * invs;
            slw [w4][idx][fq] = at * gg[(size_t)p*8+fq];
            slw2[w4][idx][fq] = at * gg[(size_t)p*8+4+fq];
        }
    }
    __syncwarp();

    // pass 2: aggregation using only v0 (32 B per edge)
    float4 a0 = make_float4(0,0,0,0), a1 = a0, a2 = a0, a3 = a0;
    for (int sl = 0; sl < deg; sl++) {
        int p = base + sl;
        int j = g_colb[p];
        const uint2* vp = (const uint2*)g_vh + (size_t)j*100;
        float4 v0 = h2f4(vp[fq]);
        float wv  = slw [w4][sl][fq];
        float w2v = slw2[w4][sl][fq];
        float shv = (lane < 25) ? __half2float(g_shh[(size_t)p*32 + lane]) : 0.0f;
        float s0 = __shfl_sync(FULLMASK, shv, r);
        float s1 = __shfl_sync(FULLMASK, shv, r+8);
        float s2 = __shfl_sync(FULLMASK, shv, r+16);
        float s3 = __shfl_sync(FULLMASK, shv, 24);
        float t0 = fmaf(wv, s0, (r == 0) ? w2v : 0.0f);
        a0.x = fmaf(t0, v0.x, a0.x); a0.y = fmaf(t0, v0.y, a0.y);
        a0.z = fmaf(t0, v0.z, a0.z); a0.w = fmaf(t0, v0.w, a0.w);
        float t1 = wv*s1;
        a1.x = fmaf(t1, v0.x, a1.x); a1.y = fmaf(t1, v0.y, a1.y);
        a1.z = fmaf(t1, v0.z, a1.z); a1.w = fmaf(t1, v0.w, a1.w);
        float t2 = wv*s2;
        a2.x = fmaf(t2, v0.x, a2.x); a2.y = fmaf(t2, v0.y, a2.y);
        a2.z = fmaf(t2, v0.z, a2.z); a2.w = fmaf(t2, v0.w, a2.w);
        if (lane < 4) {
            float t3 = wv*s3;
            a3.x = fmaf(t3, v0.x, a3.x); a3.y = fmaf(t3, v0.y, a3.y);
            a3.z = fmaf(t3, v0.z, a3.z); a3.w = fmaf(t3, v0.w, a3.w);
        }
    }

    int cb = fq*4;
    aggS[w4][r   ][cb+0]=a0.x; aggS[w4][r   ][cb+1]=a0.y; aggS[w4][r   ][cb+2]=a0.z; aggS[w4][r   ][cb+3]=a0.w;
    aggS[w4][r+8 ][cb+0]=a1.x; aggS[w4][r+8 ][cb+1]=a1.y; aggS[w4][r+8 ][cb+2]=a1.z; aggS[w4][r+8 ][cb+3]=a1.w;
    aggS[w4][r+16][cb+0]=a2.x; aggS[w4][r+16][cb+1]=a2.y; aggS[w4][r+16][cb+2]=a2.z; aggS[w4][r+16][cb+3]=a2.w;
    if (lane < 4) {
        aggS[w4][24][cb+0]=a3.x; aggS[w4][24][cb+1]=a3.y; aggS[w4][24][cb+2]=a3.z; aggS[w4][24][cb+3]=a3.w;
    }
    __syncwarp();

    float* yp = y + (size_t)node*400;
    #pragma unroll
    for (int c = 0; c < 4; c++) {
        int l = r + 8*c;
        if (c == 3) { if (lane >= 4) break; l = 24; }
        float4 o = make_float4(0,0,0,0);
        #pragma unroll
        for (int f2 = 0; f2 < 16; f2++) {
            float af = aggS[w4][l][f2];
            float4 wr = *(const float4*)&wo[f2*16 + cb];
            o.x = fmaf(af, wr.x, o.x); o.y = fmaf(af, wr.y, o.y);
            o.z = fmaf(af, wr.z, o.z); o.w = fmaf(af, wr.w, o.w);
        }
        float4 yv = *(const float4*)&yp[l*16 + cb];
        yv.x += o.x; yv.y += o.y; yv.z += o.z; yv.w += o.w;
        *(float4*)&yp[l*16 + cb] = yv;
    }
}

// ---------------- 4: full q/k/v projection, one matrix per block ----------------
__global__ void __launch_bounds__(256) k_proj(const float* __restrict__ y,
                                              const float* __restrict__ Wq,
                                              const float* __restrict__ Wk,
                                              const float* __restrict__ Wv) {
    __shared__ float4 sw[64];
    int tid = threadIdx.x;
    int m = blockIdx.y;
    const float* W = (m == 0) ? Wq : ((m == 1) ? Wk : Wv);
    if (tid < 64) sw[tid] = ((const float4*)W)[tid];
    __syncthreads();

    int r = blockIdx.x*256 + tid;
    if (r >= RPROJ) return;

    const float4* yr4 = (const float4*)(y + (size_t)r*16);
    float4 y0 = yr4[0], y1 = yr4[1], y2 = yr4[2], y3 = yr4[3];
    float yr[16] = {y0.x,y0.y,y0.z,y0.w, y1.x,y1.y,y1.z,y1.w,
                    y2.x,y2.y,y2.z,y2.w, y3.x,y3.y,y3.z,y3.w};

    float4 a0 = make_float4(0,0,0,0), a1 = a0, a2 = a0, a3 = a0;
    #pragma unroll
    for (int f = 0; f < 16; f++) {
        float yv = yr[f];
        fma4(a0, yv, sw[f*4+0]);
        fma4(a1, yv, sw[f*4+1]);
        fma4(a2, yv, sw[f*4+2]);
        fma4(a3, yv, sw[f*4+3]);
    }
    __half* out = (m == 0) ? g_qh : ((m == 1) ? g_kh : g_vh);
    uint4* o4 = (uint4*)(out + (size_t)r*16);
    uint2 p0, p1;
    p0 = pack4(a0); p1 = pack4(a1); o4[0] = make_uint4(p0.x,p0.y,p1.x,p1.y);
    p0 = pack4(a2); p1 = pack4(a3); o4[1] = make_uint4(p0.x,p0.y,p1.x,p1.y);
}

// ---------------- 5: full attention step 1 + final embed, block per node ----------------
__global__ void __launch_bounds__(128) k_attn1(const float* __restrict__ Wo,
                                               const float* __restrict__ We,
                                               const float* __restrict__ be,
                                               const float* __restrict__ emb,
                                               const int* __restrict__ Z,
                                               float* __restrict__ y) {
    __shared__ float wo[256];
    __shared__ float sWe[256];
    __shared__ float slw [BCAP][4];
    __shared__ float slw2[BCAP][4];
    __shared__ float aggS[25][17];
    int tid = threadIdx.x;
    wo[tid]      = Wo[tid];
    wo[tid+128]  = Wo[tid+128];
    sWe[tid]     = We[tid];
    sWe[tid+128] = We[tid+128];

    int w4 = tid >> 5, lane = tid & 31;
    int node = blockIdx.x;
    int deg = min(g_cnt[node], BCAP);
    int base = node*BCAP;
    __syncthreads();

    // pass 1: logits; warps split edges 4-way, q in registers
    {
        const uint2* qp = (const uint2*)g_qh + (size_t)node*100;
        float4 q0 = h2f4(qp[lane]), q1 = h2f4(qp[lane+32]), q2 = h2f4(qp[lane+64]);
        float4 q3 = (lane < 4) ? h2f4(qp[lane+96]) : make_float4(0,0,0,0);
        const float* eb = g_eb[1];

        for (int sl = w4; sl < deg; sl += 4) {
            int p = base + sl;
            int j0 = g_colb[p];
            const uint2* kp0 = (const uint2*)g_kh + (size_t)j0*100;
            float pa = dot4(q0,h2f4(kp0[lane])) + dot4(q1,h2f4(kp0[lane+32]))
                     + dot4(q2,h2f4(kp0[lane+64]));
            if (lane < 4) pa += dot4(q3, h2f4(kp0[lane+96]));
            pa += __shfl_xor_sync(FULLMASK, pa, 4);
            pa += __shfl_xor_sync(FULLMASK, pa, 8);
            pa += __shfl_xor_sync(FULLMASK, pa, 16);
            if (lane < 4)
                slw[sl][lane] = fmaf(pa, 0.1f, eb[(size_t)p*4+lane]);
        }
    }
    __syncthreads();

    // softmax: warp w4 handles head h = w4
    {
        int h = w4;
        float mx = -CUDART_INF_F;
        for (int idx = lane; idx < deg; idx += 32)
            mx = fmaxf(mx, slw[idx][h]);
        #pragma unroll
        for (int o = 16; o >= 1; o >>= 1)
            mx = fmaxf(mx, __shfl_xor_sync(FULLMASK, mx, o));
        float sacc = 0.0f;
        for (int idx = lane; idx < deg; idx += 32)
            sacc += __expf(slw[idx][h] - mx);
        #pragma unroll
        for (int o = 16; o >= 1; o >>= 1)
            sacc += __shfl_xor_sync(FULLMASK, sacc, o);
        float invs = 1.0f/(sacc + 1e-9f);
        const float* gg = g_egg[1];
        for (int idx = lane; idx < deg; idx += 32) {
            int p = base + idx;
            float at = __expf(slw[idx][h] - mx) * invs;
            slw [idx][h] = at * gg[(size_t)p*8+h];
            slw2[idx][h] = at * gg[(size_t)p*8+4+h];
        }
    }
    __syncthreads();

    // pass 2: aggregation; warps split l-rows (7/6/6/6)
    int lbase = (w4 == 0) ? 0 : 7 + (w4-1)*6;
    int R = (w4 == 0) ? 7 : 6;
    int r = lane >> 2, fq = lane & 3;   // fq == head (FH=4)
    bool act = (r < R);
    int lrow = lbase + (act ? r : 0);

    float4 acc = make_float4(0,0,0,0);
    #pragma unroll 2
    for (int sl = 0; sl < deg; sl++) {
        int p = base + sl;
        int j = g_colb[p];
        const uint2* vp = (const uint2*)g_vh + (size_t)j*100;
        float wv  = slw [sl][fq];
        float w2v = slw2[sl][fq];
        float shv = __half2float(g_shh[(size_t)p*32 + lrow]);
        float4 v0 = h2f4(vp[fq]);
        float4 vA = h2f4(vp[lrow*4 + fq]);
        float c = wv*shv;
        acc.x = fmaf(c, v0.x, fmaf(w2v, vA.x, acc.x));
        acc.y = fmaf(c, v0.y, fmaf(w2v, vA.y, acc.y));
        acc.z = fmaf(c, v0.z, fmaf(w2v, vA.z, acc.z));
        acc.w = fmaf(c, v0.w, fmaf(w2v, vA.w, acc.w));
    }
    if (act) {
        aggS[lrow][fq*4+0] = acc.x;
        aggS[lrow][fq*4+1] = acc.y;
        aggS[lrow][fq*4+2] = acc.z;
        aggS[lrow][fq*4+3] = acc.w;
    }
    __syncwarp();

    // epilogue: y += agg @ Wo ; fuse final embed on row 0
    if (act) {
        float* yp = y + (size_t)node*400;
        float4 o = make_float4(0,0,0,0);
        #pragma unroll
        for (int f = 0; f < 16; f++) {
            float af = aggS[lrow][f];
            float4 wr = *(const float4*)&wo[f*16 + fq*4];
            o.x = fmaf(af, wr.x, o.x); o.y = fmaf(af, wr.y, o.y);
            o.z = fmaf(af, wr.z, o.z); o.w = fmaf(af, wr.w, o.w);
        }
        if (lrow == 0) {
            int z = Z[node];
            float4 add = *(const float4*)&be[fq*4];
            #pragma unroll
            for (int f = 0; f < 16; f++) {
                float ev = __ldg(&emb[z*16+f]);
                float4 wr = *(const float4*)&sWe[f*16 + fq*4];
                add.x = fmaf(ev, wr.x, add.x); add.y = fmaf(ev, wr.y, add.y);
                add.z = fmaf(ev, wr.z, add.z); add.w = fmaf(ev, wr.w, add.w);
            }
            o.x += add.x; o.y += add.y; o.z += add.z; o.w += add.w;
        }
        float4 yv = *(const float4*)&yp[lrow*16 + fq*4];
        yv.x += o.x; yv.y += o.y; yv.z += o.z; yv.w += o.w;
        *(float4*)&yp[lrow*16 + fq*4] = yv;
    }

    // restore invariant for next graph replay
    if (tid == 0) g_cnt[node] = 0;
}

// ---------------- launch ----------------
extern "C" void kernel_launch(void* const* d_in, const int* in_sizes, int n_in,
                              void* d_out, int out_size) {
    const int*   Z    = (const int*)d_in[0];
    const int2*  ni   = (const int2*)d_in[1];
    const float* disp = (const float*)d_in[2];
    const float* emb  = (const float*)d_in[3];
    const float* We   = (const float*)d_in[4];
    const float* be   = (const float*)d_in[5];
    const float* Wrb  = (const float*)d_in[6];
    const float* Wq   = (const float*)d_in[7];
    const float* Wk   = (const float*)d_in[8];
    const float* Wv   = (const float*)d_in[9];
    const float* Wo   = (const float*)d_in[10];
    const float* Wb   = (const float*)d_in[11];
    const float* Wg   = (const float*)d_in[12];
    const float* Wg2  = (const float*)d_in[13];
    float* y = (float*)d_out;

    k_build_geom<<<(EE+255)/256, 256>>>(ni, disp, Wb, Wg, Wg2);
    k_initproj0 <<<NN/4, 128>>>(emb, Wrb, Wq, Wk, Wv, Z, y);
    k_attn0     <<<NN/4, 128>>>(Wo, y);
    k_proj      <<<dim3((RPROJ+255)/256, 3), 256>>>(y, Wq+256, Wk+256, Wv+256);
    k_attn1     <<<NN, 128>>>(Wo+256, We, be, emb, Z, y);
}

// round 17
// speedup vs baseline: 1.3249x; 1.0574x over previous
#include <cuda_runtime.h>
#include <cuda_fp16.h>
#include <math_constants.h>
#include <cstdint>

#define NN 10000
#define EE 160000
#define RPROJ (NN*25)
#define BCAP 72
#define NP (NN*BCAP)
#define FULLMASK 0xffffffffu

// ---------------- scratch ----------------
__device__ int   g_cnt[NN];            // degree; zeroed by k_attn1 each run
__device__ int   g_colb[NP];           // bucketed neighbor j
__device__ float g_rbf[(size_t)NP*16];
__device__ __align__(16) __half g_shh[(size_t)NP*32];  // 25 used, padded to 32 halves
__device__ __align__(16) __half g_eb[2][(size_t)NP*4];
__device__ __align__(16) __half g_egg[2][(size_t)NP*8];
__device__ __align__(16) __half g_qh[(size_t)RPROJ*16];
__device__ __align__(16) __half g_kh[(size_t)RPROJ*16];
__device__ __align__(16) __half g_vh[(size_t)RPROJ*16];

// ---------------- helpers ----------------
__device__ __forceinline__ float dot4(float4 a, float4 b) {
    return fmaf(a.x,b.x, fmaf(a.y,b.y, fmaf(a.z,b.z, a.w*b.w)));
}
__device__ __forceinline__ float4 h2f4(uint2 u) {
    __half2 a = *(__half2*)&u.x;
    __half2 b = *(__half2*)&u.y;
    float2 fa = __half22float2(a), fb = __half22float2(b);
    return make_float4(fa.x, fa.y, fb.x, fb.y);
}
__device__ __forceinline__ void fma4(float4& acc, float s, float4 w) {
    acc.x = fmaf(s, w.x, acc.x); acc.y = fmaf(s, w.y, acc.y);
    acc.z = fmaf(s, w.z, acc.z); acc.w = fmaf(s, w.w, acc.w);
}
__device__ __forceinline__ uint2 pack4(float4 a) {
    uint2 o;
    __half2 lo = __floats2half2_rn(a.x, a.y);
    __half2 hi = __floats2half2_rn(a.z, a.w);
    o.x = *(unsigned*)&lo; o.y = *(unsigned*)&hi;
    return o;
}
__device__ __forceinline__ unsigned h2u(__half2 v) { return *(unsigned*)&v; }

// ---------------- 1: bucket build + geometry + edge scalars ----------------
__global__ void __launch_bounds__(256) k_build_geom(const int2* __restrict__ ni,
                                                    const float* __restrict__ disp,
                                                    const float* __restrict__ Wb,
                                                    const float* __restrict__ Wg,
                                                    const float* __restrict__ Wg2) {
    __shared__ float4 sW4[96];   // [t][s][f] : t*32 + s*16 + f
    int tid = threadIdx.x;
    if (tid < 32)       sW4[tid] = ((const float4*)Wb)[tid];
    else if (tid < 64)  sW4[tid] = ((const float4*)Wg)[tid-32];
    else if (tid < 96)  sW4[tid] = ((const float4*)Wg2)[tid-64];
    __syncthreads();

    int e = blockIdx.x*256 + tid;
    if (e >= EE) return;
    int2 pr = ni[e];
    int i = pr.x, j = pr.y;
    int slot = atomicAdd(&g_cnt[i], 1);
    if (slot >= BCAP) return;          // statistically impossible for Poisson(16)
    int p = i*BCAP + slot;
    g_colb[p] = j;

    float dx = disp[3*e], dy = disp[3*e+1], dz = disp[3*e+2];
    float d  = sqrtf(dx*dx + dy*dy + dz*dz);
    float ds = fmaxf(d, 1e-9f);
    float inv = 1.0f/ds;
    float x = dx*inv, y = dy*inv, z = dz*inv;

    float env = 0.5f*(cospif(fminf(ds, 5.0f)*0.2f) + 1.0f);
    float t = ds*0.2f;
    float rbf[16];
    if (t < 1e-7f) {
        #pragma unroll
        for (int kk = 0; kk < 16; kk++) rbf[kk] = env;
    } else {
        float s1, c1;
        sincospif(t, &s1, &c1);
        float twoc = 2.0f*c1;
        float invt = env / (CUDART_PI_F * t);
        float skm = 0.0f, sk = s1;
        #pragma unroll
        for (int kk = 0; kk < 16; kk++) {
            rbf[kk] = sk * invt * (1.0f/(float)(kk+1));
            float nx = twoc*sk - skm;
            skm = sk; sk = nx;
        }
    }
    float4* rp = (float4*)(g_rbf + (size_t)p*16);
    rp[0] = make_float4(rbf[0],rbf[1],rbf[2],rbf[3]);
    rp[1] = make_float4(rbf[4],rbf[5],rbf[6],rbf[7]);
    rp[2] = make_float4(rbf[8],rbf[9],rbf[10],rbf[11]);
    rp[3] = make_float4(rbf[12],rbf[13],rbf[14],rbf[15]);

    #pragma unroll
    for (int s = 0; s < 2; s++) {
        float4 ab = make_float4(0,0,0,0), ag = ab, ag2 = ab;
        #pragma unroll
        for (int f = 0; f < 16; f++) {
            float rv = rbf[f];
            fma4(ab,  rv, sW4[s*16+f]);
            fma4(ag,  rv, sW4[32+s*16+f]);
            fma4(ag2, rv, sW4[64+s*16+f]);
        }
        uint2 ebp = pack4(ab);
        *(uint2*)(g_eb[s] + (size_t)p*4) = ebp;
        uint2 g1p = pack4(ag), g2p = pack4(ag2);
        *(uint4*)(g_egg[s] + (size_t)p*8) = make_uint4(g1p.x, g1p.y, g2p.x, g2p.y);
    }

    float x2 = x*x, y2 = y*y, z2 = z*z;
    float sh[25];
    sh[0]  = 0.28209479177387814f;
    sh[1]  = 0.4886025119029199f*y;
    sh[2]  = 0.4886025119029199f*z;
    sh[3]  = 0.4886025119029199f*x;
    sh[4]  = 1.0925484305920792f*x*y;
    sh[5]  = 1.0925484305920792f*y*z;
    sh[6]  = 0.31539156525252005f*(3.0f*z2 - 1.0f);
    sh[7]  = 1.0925484305920792f*x*z;
    sh[8]  = 0.5462742152960396f*(x2 - y2);
    sh[9]  = 0.5900435899266435f*y*(3.0f*x2 - y2);
    sh[10] = 2.890611442640554f*x*y*z;
    sh[11] = 0.4570457994644658f*y*(5.0f*z2 - 1.0f);
    sh[12] = 0.3731763325901154f*z*(5.0f*z2 - 3.0f);
    sh[13] = 0.4570457994644658f*x*(5.0f*z2 - 1.0f);
    sh[14] = 1.445305721320277f*z*(x2 - y2);
    sh[15] = 0.5900435899266435f*x*(x2 - 3.0f*y2);
    sh[16] = 2.5033429417967046f*x*y*(x2 - y2);
    sh[17] = 1.7701307697799304f*y*z*(3.0f*x2 - y2);
    sh[18] = 0.9461746957575601f*x*y*(7.0f*z2 - 1.0f);
    sh[19] = 0.6690465435572892f*y*z*(7.0f*z2 - 3.0f);
    sh[20] = 0.10578554691520431f*(35.0f*z2*z2 - 30.0f*z2 + 3.0f);
    sh[21] = 0.6690465435572892f*x*z*(7.0f*z2 - 3.0f);
    sh[22] = 0.47308734787878004f*(x2 - y2)*(7.0f*z2 - 1.0f);
    sh[23] = 1.7701307697799304f*x*z*(x2 - 3.0f*y2);
    sh[24] = 0.6258357354491761f*(x2*x2 - 6.0f*x2*y2 + y2*y2);

    unsigned hp[13];
    #pragma unroll
    for (int ii = 0; ii < 12; ii++)
        hp[ii] = h2u(__floats2half2_rn(sh[2*ii], sh[2*ii+1]));
    hp[12] = h2u(__floats2half2_rn(sh[24], 0.0f));
    uint4* o4 = (uint4*)(g_shh + (size_t)p*32);
    o4[0] = make_uint4(hp[0], hp[1], hp[2], hp[3]);
    o4[1] = make_uint4(hp[4], hp[5], hp[6], hp[7]);
    o4[2] = make_uint4(hp[8], hp[9], hp[10], hp[11]);
    o4[3] = make_uint4(hp[12], 0u, 0u, 0u);
}

// ---------------- 2: y0 init + step-0 q/k/v projection (row 0 only) ----------------
__global__ void __launch_bounds__(128) k_initproj0(const float* __restrict__ emb,
                                                   const float* __restrict__ Wrb,
                                                   const float* __restrict__ Wq0,
                                                   const float* __restrict__ Wk0,
                                                   const float* __restrict__ Wv0,
                                                   const int* __restrict__ Z,
                                                   float* __restrict__ y) {
    int tid = threadIdx.x;
    int w = tid >> 5, lane = tid & 31;
    int node = blockIdx.x*4 + w;
    int f = lane & 15, which = lane >> 4;
    int deg = min(g_cnt[node], BCAP);
    int base = node*BCAP;

    float acc = 0.0f;
    for (int sl = which; sl < deg; sl += 2) {
        int p = base + sl;
        int j = g_colb[p];
        int z = Z[j];
        acc = fmaf(g_rbf[(size_t)p*16+f], __ldg(&emb[z*16+f]), acc);
    }
    acc += __shfl_xor_sync(FULLMASK, acc, 16);
    float y0 = 0.0f;
    #pragma unroll
    for (int ff = 0; ff < 16; ff++)
        y0 = fmaf(__shfl_sync(FULLMASK, acc, ff), __ldg(&Wrb[ff*16+f]), y0);

    float* yp = y + (size_t)node*400;
    if (lane < 16) yp[f] = y0;
    float4* yz = (float4*)(yp + 16);
    #pragma unroll
    for (int idx = lane; idx < 96; idx += 32) yz[idx] = make_float4(0,0,0,0);

    // q0 (half A) / k0 (half B), v0 (half A)
    const float* Wqk = (which == 0) ? Wq0 : Wk0;
    float oq = 0.0f, ov = 0.0f;
    #pragma unroll
    for (int ff = 0; ff < 16; ff++) {
        float yv = __shfl_sync(FULLMASK, y0, ff);
        oq = fmaf(yv, __ldg(&Wqk[ff*16+f]), oq);
        ov = fmaf(yv, __ldg(&Wv0[ff*16+f]), ov);
    }
    size_t ro = (size_t)node*400;
    if (which == 0) {
        g_qh[ro+f] = __float2half_rn(oq);
        g_vh[ro+f] = __float2half_rn(ov);
    } else {
        g_kh[ro+f] = __float2half_rn(oq);
    }
}

// ---------------- 3: step-0 attention; pass 1 lane-per-edge ----------------
__global__ void __launch_bounds__(128) k_attn0(const float* __restrict__ Wo,
                                               float* __restrict__ y) {
    __shared__ float wo[256];
    __shared__ float slw [4][BCAP][4];
    __shared__ float slw2[4][BCAP][4];
    __shared__ float aggS[4][25][17];
    int tid = threadIdx.x;
    wo[tid]     = Wo[tid];
    wo[tid+128] = Wo[tid+128];

    int w4 = tid >> 5, lane = tid & 31;
    int node = blockIdx.x*4 + w4;
    int r = lane >> 2, fq = lane & 3;
    int deg = min(g_cnt[node], BCAP);
    int base = node*BCAP;
    __syncthreads();

    const uint2* qp = (const uint2*)g_qh + (size_t)node*100;
    float4 q0v = h2f4(qp[fq]);
    const __half* eb = g_eb[0];

    // pass 1: logits; lane (g=r, fq) handles edge sl0+r entirely in-lane
    for (int sl0 = 0; sl0 < deg; sl0 += 8) {
        int sl = sl0 + r;
        if (sl < deg) {
            int p = base + sl;
            int j = g_colb[p];
            const uint2* kp = (const uint2*)g_kh + (size_t)j*100;
            float4 k0v = h2f4(kp[fq]);
            slw[w4][sl][fq] = fmaf(dot4(q0v, k0v), 0.1f,
                                   __half2float(eb[(size_t)p*4+fq]));
        }
    }
    __syncwarp();

    // softmax + premultiplied weights
    {
        float mx = -CUDART_INF_F;
        for (int idx = r; idx < deg; idx += 8)
            mx = fmaxf(mx, slw[w4][idx][fq]);
        mx = fmaxf(mx, __shfl_xor_sync(FULLMASK, mx, 4));
        mx = fmaxf(mx, __shfl_xor_sync(FULLMASK, mx, 8));
        mx = fmaxf(mx, __shfl_xor_sync(FULLMASK, mx, 16));
        float sacc = 0.0f;
        for (int idx = r; idx < deg; idx += 8)
            sacc += __expf(slw[w4][idx][fq] - mx);
        sacc += __shfl_xor_sync(FULLMASK, sacc, 4);
        sacc += __shfl_xor_sync(FULLMASK, sacc, 8);
        sacc += __shfl_xor_sync(FULLMASK, sacc, 16);
        float invs = 1.0f/(sacc + 1e-9f);
        const __half* gg = g_egg[0];
        for (int idx = r; idx < deg; idx += 8) {
            int p = base + idx;
            float at = __expf(slw[w4][idx][fq] - mx) * invs;
            slw [w4][idx][fq] = at * __half2float(gg[(size_t)p*8+fq]);
            slw2[w4][idx][fq] = at * __half2float(gg[(size_t)p*8+4+fq]);
        }
    }
    __syncwarp();

    // pass 2: aggregation using only v0 (32 B per edge)
    float4 a0 = make_float4(0,0,0,0), a1 = a0, a2 = a0, a3 = a0;
    for (int sl = 0; sl < deg; sl++) {
        int p = base + sl;
        int j = g_colb[p];
        const uint2* vp = (const uint2*)g_vh + (size_t)j*100;
        float4 v0 = h2f4(vp[fq]);
        float wv  = slw [w4][sl][fq];
        float w2v = slw2[w4][sl][fq];
        float shv = (lane < 25) ? __half2float(g_shh[(size_t)p*32 + lane]) : 0.0f;
        float s0 = __shfl_sync(FULLMASK, shv, r);
        float s1 = __shfl_sync(FULLMASK, shv, r+8);
        float s2 = __shfl_sync(FULLMASK, shv, r+16);
        float s3 = __shfl_sync(FULLMASK, shv, 24);
        float t0 = fmaf(wv, s0, (r == 0) ? w2v : 0.0f);
        a0.x = fmaf(t0, v0.x, a0.x); a0.y = fmaf(t0, v0.y, a0.y);
        a0.z = fmaf(t0, v0.z, a0.z); a0.w = fmaf(t0, v0.w, a0.w);
        float t1 = wv*s1;
        a1.x = fmaf(t1, v0.x, a1.x); a1.y = fmaf(t1, v0.y, a1.y);
        a1.z = fmaf(t1, v0.z, a1.z); a1.w = fmaf(t1, v0.w, a1.w);
        float t2 = wv*s2;
        a2.x = fmaf(t2, v0.x, a2.x); a2.y = fmaf(t2, v0.y, a2.y);
        a2.z = fmaf(t2, v0.z, a2.z); a2.w = fmaf(t2, v0.w, a2.w);
        if (lane < 4) {
            float t3 = wv*s3;
            a3.x = fmaf(t3, v0.x, a3.x); a3.y = fmaf(t3, v0.y, a3.y);
            a3.z = fmaf(t3, v0.z, a3.z); a3.w = fmaf(t3, v0.w, a3.w);
        }
    }

    int cb = fq*4;
    aggS[w4][r   ][cb+0]=a0.x; aggS[w4][r   ][cb+1]=a0.y; aggS[w4][r   ][cb+2]=a0.z; aggS[w4][r   ][cb+3]=a0.w;
    aggS[w4][r+8 ][cb+0]=a1.x; aggS[w4][r+8 ][cb+1]=a1.y; aggS[w4][r+8 ][cb+2]=a1.z; aggS[w4][r+8 ][cb+3]=a1.w;
    aggS[w4][r+16][cb+0]=a2.x; aggS[w4][r+16][cb+1]=a2.y; aggS[w4][r+16][cb+2]=a2.z; aggS[w4][r+16][cb+3]=a2.w;
    if (lane < 4) {
        aggS[w4][24][cb+0]=a3.x; aggS[w4][24][cb+1]=a3.y; aggS[w4][24][cb+2]=a3.z; aggS[w4][24][cb+3]=a3.w;
    }
    __syncwarp();

    float* yp = y + (size_t)node*400;
    #pragma unroll
    for (int c = 0; c < 4; c++) {
        int l = r + 8*c;
        if (c == 3) { if (lane >= 4) break; l = 24; }
        float4 o = make_float4(0,0,0,0);
        #pragma unroll
        for (int f2 = 0; f2 < 16; f2++) {
            float af = aggS[w4][l][f2];
            float4 wr = *(const float4*)&wo[f2*16 + cb];
            o.x = fmaf(af, wr.x, o.x); o.y = fmaf(af, wr.y, o.y);
            o.z = fmaf(af, wr.z, o.z); o.w = fmaf(af, wr.w, o.w);
        }
        float4 yv = *(const float4*)&yp[l*16 + cb];
        yv.x += o.x; yv.y += o.y; yv.z += o.z; yv.w += o.w;
        *(float4*)&yp[l*16 + cb] = yv;
    }
}

// ---------------- 4: full q/k/v projection, thread per row, sequential q/k/v ----------------
__global__ void __launch_bounds__(256) k_proj(const float* __restrict__ y,
                                              const float* __restrict__ Wq,
                                              const float* __restrict__ Wk,
                                              const float* __restrict__ Wv) {
    __shared__ float4 sw[192];   // q:[0,64) k:[64,128) v:[128,192)
    int tid = threadIdx.x;
    if (tid < 64)        sw[tid]     = ((const float4*)Wq)[tid];
    else if (tid < 128)  sw[tid]     = ((const float4*)Wk)[tid-64];
    else if (tid < 192)  sw[tid]     = ((const float4*)Wv)[tid-128];
    __syncthreads();

    int r = blockIdx.x*256 + tid;
    if (r >= RPROJ) return;

    const float4* yr4 = (const float4*)(y + (size_t)r*16);
    float4 y0 = yr4[0], y1 = yr4[1], y2 = yr4[2], y3 = yr4[3];
    float yr[16] = {y0.x,y0.y,y0.z,y0.w, y1.x,y1.y,y1.z,y1.w,
                    y2.x,y2.y,y2.z,y2.w, y3.x,y3.y,y3.z,y3.w};

    __half* outs[3] = { g_qh, g_kh, g_vh };
    #pragma unroll
    for (int m = 0; m < 3; m++) {
        const float4* W = sw + m*64;
        float4 a0 = make_float4(0,0,0,0), a1 = a0, a2 = a0, a3 = a0;
        #pragma unroll
        for (int f = 0; f < 16; f++) {
            float yv = yr[f];
            fma4(a0, yv, W[f*4+0]);
            fma4(a1, yv, W[f*4+1]);
            fma4(a2, yv, W[f*4+2]);
            fma4(a3, yv, W[f*4+3]);
        }
        uint4* o4 = (uint4*)(outs[m] + (size_t)r*16);
        uint2 p0, p1;
        p0 = pack4(a0); p1 = pack4(a1); o4[0] = make_uint4(p0.x,p0.y,p1.x,p1.y);
        p0 = pack4(a2); p1 = pack4(a3); o4[1] = make_uint4(p0.x,p0.y,p1.x,p1.y);
    }
}

// ---------------- 5: full attention step 1 + final embed, block per node ----------------
__global__ void __launch_bounds__(128) k_attn1(const float* __restrict__ Wo,
                                               const float* __restrict__ We,
                                               const float* __restrict__ be,
                                               const float* __restrict__ emb,
                                               const int* __restrict__ Z,
                                               float* __restrict__ y) {
    __shared__ float wo[256];
    __shared__ float sWe[256];
    __shared__ float slw [BCAP][4];
    __shared__ float slw2[BCAP][4];
    __shared__ float aggS[25][17];
    int tid = threadIdx.x;
    wo[tid]      = Wo[tid];
    wo[tid+128]  = Wo[tid+128];
    sWe[tid]     = We[tid];
    sWe[tid+128] = We[tid+128];

    int w4 = tid >> 5, lane = tid & 31;
    int node = blockIdx.x;
    int deg = min(g_cnt[node], BCAP);
    int base = node*BCAP;
    __syncthreads();

    // pass 1: logits; warps split edges 4-way, q in registers
    {
        const uint2* qp = (const uint2*)g_qh + (size_t)node*100;
        float4 q0 = h2f4(qp[lane]), q1 = h2f4(qp[lane+32]), q2 = h2f4(qp[lane+64]);
        float4 q3 = (lane < 4) ? h2f4(qp[lane+96]) : make_float4(0,0,0,0);
        const __half* eb = g_eb[1];

        for (int sl = w4; sl < deg; sl += 4) {
            int p = base + sl;
            int j0 = g_colb[p];
            const uint2* kp0 = (const uint2*)g_kh + (size_t)j0*100;
            float pa = dot4(q0,h2f4(kp0[lane])) + dot4(q1,h2f4(kp0[lane+32]))
                     + dot4(q2,h2f4(kp0[lane+64]));
            if (lane < 4) pa += dot4(q3, h2f4(kp0[lane+96]));
            pa += __shfl_xor_sync(FULLMASK, pa, 4);
            pa += __shfl_xor_sync(FULLMASK, pa, 8);
            pa += __shfl_xor_sync(FULLMASK, pa, 16);
            if (lane < 4)
                slw[sl][lane] = fmaf(pa, 0.1f, __half2float(eb[(size_t)p*4+lane]));
        }
    }
    __syncthreads();

    // softmax: warp w4 handles head h = w4
    {
        int h = w4;
        float mx = -CUDART_INF_F;
        for (int idx = lane; idx < deg; idx += 32)
            mx = fmaxf(mx, slw[idx][h]);
        #pragma unroll
        for (int o = 16; o >= 1; o >>= 1)
            mx = fmaxf(mx, __shfl_xor_sync(FULLMASK, mx, o));
        float sacc = 0.0f;
        for (int idx = lane; idx < deg; idx += 32)
            sacc += __expf(slw[idx][h] - mx);
        #pragma unroll
        for (int o = 16; o >= 1; o >>= 1)
            sacc += __shfl_xor_sync(FULLMASK, sacc, o);
        float invs = 1.0f/(sacc + 1e-9f);
        const __half* gg = g_egg[1];
        for (int idx = lane; idx < deg; idx += 32) {
            int p = base + idx;
            float at = __expf(slw[idx][h] - mx) * invs;
            slw [idx][h] = at * __half2float(gg[(size_t)p*8+h]);
            slw2[idx][h] = at * __half2float(gg[(size_t)p*8+4+h]);
        }
    }
    __syncthreads();

    // pass 2: aggregation; warps split l-rows (7/6/6/6)
    int lbase = (w4 == 0) ? 0 : 7 + (w4-1)*6;
    int R = (w4 == 0) ? 7 : 6;
    int r = lane >> 2, fq = lane & 3;   // fq == head (FH=4)
    bool act = (r < R);
    int lrow = lbase + (act ? r : 0);

    float4 acc = make_float4(0,0,0,0);
    #pragma unroll 2
    for (int sl = 0; sl < deg; sl++) {
        int p = base + sl;
        int j = g_colb[p];
        const uint2* vp = (const uint2*)g_vh + (size_t)j*100;
        float wv  = slw [sl][fq];
        float w2v = slw2[sl][fq];
        float shv = __half2float(g_shh[(size_t)p*32 + lrow]);
        float4 v0 = h2f4(vp[fq]);
        float4 vA = h2f4(vp[lrow*4 + fq]);
        float c = wv*shv;
        acc.x = fmaf(c, v0.x, fmaf(w2v, vA.x, acc.x));
        acc.y = fmaf(c, v0.y, fmaf(w2v, vA.y, acc.y));
        acc.z = fmaf(c, v0.z, fmaf(w2v, vA.z, acc.z));
        acc.w = fmaf(c, v0.w, fmaf(w2v, vA.w, acc.w));
    }
    if (act) {
        aggS[lrow][fq*4+0] = acc.x;
        aggS[lrow][fq*4+1] = acc.y;
        aggS[lrow][fq*4+2] = acc.z;
        aggS[lrow][fq*4+3] = acc.w;
    }
    __syncwarp();

    // epilogue: y += agg @ Wo ; fuse final embed on row 0
    if (act) {
        float* yp = y + (size_t)node*400;
        float4 o = make_float4(0,0,0,0);
        #pragma unroll
        for (int f = 0; f < 16; f++) {
            float af = aggS[lrow][f];
            float4 wr = *(const float4*)&wo[f*16 + fq*4];
            o.x = fmaf(af, wr.x, o.x); o.y = fmaf(af, wr.y, o.y);
            o.z = fmaf(af, wr.z, o.z); o.w = fmaf(af, wr.w, o.w);
        }
        if (lrow == 0) {
            int z = Z[node];
            float4 add = *(const float4*)&be[fq*4];
            #pragma unroll
            for (int f = 0; f < 16; f++) {
                float ev = __ldg(&emb[z*16+f]);
                float4 wr = *(const float4*)&sWe[f*16 + fq*4];
                add.x = fmaf(ev, wr.x, add.x); add.y = fmaf(ev, wr.y, add.y);
                add.z = fmaf(ev, wr.z, add.z); add.w = fmaf(ev, wr.w, add.w);
            }
            o.x += add.x; o.y += add.y; o.z += add.z; o.w += add.w;
        }
        float4 yv = *(const float4*)&yp[lrow*16 + fq*4];
        yv.x += o.x; yv.y += o.y; yv.z += o.z; yv.w += o.w;
        *(float4*)&yp[lrow*16 + fq*4] = yv;
    }

    // restore invariant for next graph replay
    if (tid == 0) g_cnt[node] = 0;
}

// ---------------- launch ----------------
extern "C" void kernel_launch(void* const* d_in, const int* in_sizes, int n_in,
                              void* d_out, int out_size) {
    const int*   Z    = (const int*)d_in[0];
    const int2*  ni   = (const int2*)d_in[1];
    const float* disp = (const float*)d_in[2];
    const float* emb  = (const float*)d_in[3];
    const float* We   = (const float*)d_in[4];
    const float* be   = (const float*)d_in[5];
    const float* Wrb  = (const float*)d_in[6];
    const float* Wq   = (const float*)d_in[7];
    const float* Wk   = (const float*)d_in[8];
    const float* Wv   = (const float*)d_in[9];
    const float* Wo   = (const float*)d_in[10];
    const float* Wb   = (const float*)d_in[11];
    const float* Wg   = (const float*)d_in[12];
    const float* Wg2  = (const float*)d_in[13];
    float* y = (float*)d_out;

    k_build_geom<<<(EE+255)/256, 256>>>(ni, disp, Wb, Wg, Wg2);
    k_initproj0 <<<NN/4, 128>>>(emb, Wrb, Wq, Wk, Wv, Z, y);
    k_attn0     <<<NN/4, 128>>>(Wo, y);
    k_proj      <<<(RPROJ+255)/256, 256>>>(y, Wq+256, Wk+256, Wv+256);
    k_attn1     <<<NN, 128>>>(Wo+256, We, be, emb, Z, y);
}